// round 13
// baseline (speedup 1.0000x reference)
#include <cuda_runtime.h>
#include <cuda_fp16.h>
#include <math.h>
#include <stdint.h>

#define B_    8
#define H_    8
#define LQ_   512
#define T_    8192
#define DIM_  256
#define HD_   32
#define MAXREL_ 128
#define NSPLIT 2
#define TSPLIT (T_ / NSPLIT)
#define NTILES (TSPLIT / 64)
#define STEPF (8191.0f / 511.0f)

// ---------------- scratch ----------------
__device__ __half g_Qh[B_ * LQ_ * DIM_];
__device__ __half g_KVh[B_ * T_ * 2 * DIM_];
__device__ __half g_em[LQ_ * T_];
__device__ float  g_op[NSPLIT * B_ * LQ_ * DIM_];
__device__ float  g_ml[NSPLIT * B_ * LQ_ * H_ * 2];
__device__ float  g_far[2];

// ---------------- helpers ----------------
__device__ __forceinline__ void mma_f16(float c[4], const unsigned a[4], unsigned b0, unsigned b1) {
    asm volatile("mma.sync.aligned.m16n8k16.row.col.f32.f16.f16.f32 "
        "{%0,%1,%2,%3}, {%4,%5,%6,%7}, {%8,%9}, {%0,%1,%2,%3};"
        : "+f"(c[0]), "+f"(c[1]), "+f"(c[2]), "+f"(c[3])
        : "r"(a[0]), "r"(a[1]), "r"(a[2]), "r"(a[3]), "r"(b0), "r"(b1));
}
__device__ __forceinline__ unsigned h2u(__half2 h) { return *(unsigned*)&h; }
__device__ __forceinline__ uint32_t smem_u32(const void* p) {
    uint32_t a;
    asm("{ .reg .u64 t; cvta.to.shared.u64 t, %1; cvt.u32.u64 %0, t; }" : "=r"(a) : "l"(p));
    return a;
}
__device__ __forceinline__ float ex2(float x) {
    float r; asm("ex2.approx.f32 %0, %1;" : "=f"(r) : "f"(x)); return r;
}
__device__ __forceinline__ unsigned ex2h2(unsigned x) {
    unsigned r; asm("ex2.approx.f16x2 %0, %1;" : "=r"(r) : "r"(x)); return r;
}
#define LDM_X4(r, addr) \
    asm volatile("ldmatrix.sync.aligned.m8n8.x4.shared.b16 {%0,%1,%2,%3}, [%4];" \
        : "=r"((r)[0]), "=r"((r)[1]), "=r"((r)[2]), "=r"((r)[3]) : "r"(addr))
#define LDM_X4T(r, addr) \
    asm volatile("ldmatrix.sync.aligned.m8n8.x4.trans.shared.b16 {%0,%1,%2,%3}, [%4];" \
        : "=r"((r)[0]), "=r"((r)[1]), "=r"((r)[2]), "=r"((r)[3]) : "r"(addr))
#define CP16(dst, src) \
    asm volatile("cp.async.ca.shared.global [%0], [%1], 16;" :: "r"(dst), "l"(src))
#define CP_COMMIT() asm volatile("cp.async.commit_group;" ::: "memory")
#define CP_WAIT0()  asm volatile("cp.async.wait_group 0;" ::: "memory")

#define STG_SZ 19456
#define OFF_V  5120
#define OFF_M  10240

// ---------------- exp(mask) precompute (band-restricted) + far constants ----------------
__global__ void emask_kernel(const float* __restrict__ rel_bias,
                             const float* __restrict__ mask_scale,
                             __half* __restrict__ em,
                             float* __restrict__ farc) {
    int idx = blockIdx.x * blockDim.x + threadIdx.x;
    if (idx == 0) {
        const float L2E = 1.4426950408889634f;
        float ms = mask_scale[0];
        farc[0] = ms * (rel_bias[0] + __logf(1e-6f)) * L2E;
        farc[1] = ms * (rel_bias[2 * MAXREL_] + __logf(1e-6f)) * L2E;
    }
    int i = idx >> 13;
    int t = idx & (T_ - 1);
    float tau = (float)i * STEPF;
    float dt  = (float)t - tau;
    if (fabsf(dt) > 1664.0f) return;      // never read by any mixed tile
    float dtc = fminf(fmaxf(dt, -(float)MAXREL_), (float)MAXREL_);
    int bi = (int)dtc + MAXREL_;
    float bias = rel_bias[bi];
    float z = dt * (1.0f / 64.0f);
    float lg = __logf(__expf(-0.5f * z * z) + 1e-6f);
    em[idx] = __float2half_rn(__expf(mask_scale[0] * (bias + lg)));
}

// ---------------- fp16 GEMM (half output; col tile on blockIdx.x for L2 A-reuse) ----------------
__global__ void __launch_bounds__(256, 2) gemm16(const float* __restrict__ A,
                                                 const float* __restrict__ W,
                                                 const float* __restrict__ bias,
                                                 __half* __restrict__ outp,
                                                 int ldo, float scale) {
    __shared__ __align__(16) unsigned As2[128][20];
    __shared__ __align__(16) unsigned Ws2[128][20];
    int tid = threadIdx.x;
    int lane = tid & 31, warp = tid >> 5;
    int wm = warp >> 1, wn = warp & 1;
    int g = lane >> 2, tig = lane & 3;
    int row0 = blockIdx.y * 128, col0 = blockIdx.x * 128;
    uint32_t sbA = smem_u32(&As2[0][0]);
    uint32_t sbW = smem_u32(&Ws2[0][0]);

    float c[2][8][4];
    #pragma unroll
    for (int i = 0; i < 2; i++)
        #pragma unroll
        for (int j = 0; j < 8; j++)
            #pragma unroll
            for (int v = 0; v < 4; v++) c[i][j][v] = 0.0f;

    int sm  = tid >> 3;
    int sk4 = (tid & 7) * 4;
    uint32_t aArow = (uint32_t)(wm * 32 + (lane & 7) + ((lane >> 3) & 1) * 8);
    uint32_t aAseg = (uint32_t)(lane >> 4);
    uint32_t aBrow = (uint32_t)(wn * 64 + (lane >> 3) * 8 + (lane & 7));

    for (int k0 = 0; k0 < 256; k0 += 32) {
        __syncthreads();
        #pragma unroll
        for (int it = 0; it < 4; it++) {
            int r = sm + it * 32;
            float4 a4 = *(const float4*)&A[(size_t)(row0 + r) * 256 + k0 + sk4];
            float4 w4 = *(const float4*)&W[(size_t)(col0 + r) * 256 + k0 + sk4];
            uint2 ua; ua.x = h2u(__floats2half2_rn(a4.x, a4.y)); ua.y = h2u(__floats2half2_rn(a4.z, a4.w));
            uint2 uw; uw.x = h2u(__floats2half2_rn(w4.x, w4.y)); uw.y = h2u(__floats2half2_rn(w4.z, w4.w));
            *(uint2*)&As2[r][sk4 >> 1] = ua;
            *(uint2*)&Ws2[r][sk4 >> 1] = uw;
        }
        __syncthreads();
        #pragma unroll
        for (int kc = 0; kc < 2; kc++) {
            unsigned af0[4], af1[4];
            LDM_X4(af0, sbA + aArow * 80 + (kc * 2 + aAseg) * 16);
            LDM_X4(af1, sbA + (aArow + 16) * 80 + (kc * 2 + aAseg) * 16);
            unsigned b0a[4], b1a[4], b0b[4], b1b[4];
            uint32_t aB = sbW + aBrow * 80 + kc * 32;
            LDM_X4(b0a, aB);
            LDM_X4(b1a, aB + 16);
            LDM_X4(b0b, aB + 32 * 80);
            LDM_X4(b1b, aB + 32 * 80 + 16);
            #pragma unroll
            for (int j = 0; j < 8; j++) {
                unsigned bb0 = (j < 4) ? b0a[j] : b0b[j - 4];
                unsigned bb1 = (j < 4) ? b1a[j] : b1b[j - 4];
                mma_f16(c[0][j], af0, bb0, bb1);
                mma_f16(c[1][j], af1, bb0, bb1);
            }
        }
    }

    #pragma unroll
    for (int j = 0; j < 8; j++) {
        int colg = col0 + wn * 64 + j * 8 + 2 * tig;
        float2 bv = *(const float2*)&bias[colg];
        #pragma unroll
        for (int i = 0; i < 2; i++) {
            int rowg = row0 + wm * 32 + i * 16 + g;
            float x0 = scale * (c[i][j][0] + bv.x);
            float y0 = scale * (c[i][j][1] + bv.y);
            float x1 = scale * (c[i][j][2] + bv.x);
            float y1 = scale * (c[i][j][3] + bv.y);
            *(unsigned*)&outp[(size_t)rowg * ldo + colg] = h2u(__floats2half2_rn(x0, y0));
            *(unsigned*)&outp[(size_t)(rowg + 8) * ldo + colg] = h2u(__floats2half2_rn(x1, y1));
        }
    }
}

// ---------------- out-projection GEMM with fused split merge (fp32 out) ----------------
__global__ void __launch_bounds__(256, 2) gemm_out(const float* __restrict__ opart,
                                                   const float* __restrict__ mlpart,
                                                   const float* __restrict__ W,
                                                   const float* __restrict__ bias,
                                                   float* __restrict__ outp) {
    __shared__ __align__(16) unsigned As2[128][20];
    __shared__ __align__(16) unsigned Ws2[128][20];
    int tid = threadIdx.x;
    int lane = tid & 31, warp = tid >> 5;
    int wm = warp >> 1, wn = warp & 1;
    int g = lane >> 2, tig = lane & 3;
    int row0 = blockIdx.y * 128, col0 = blockIdx.x * 128;
    uint32_t sbA = smem_u32(&As2[0][0]);
    uint32_t sbW = smem_u32(&Ws2[0][0]);

    float c[2][8][4];
    #pragma unroll
    for (int i = 0; i < 2; i++)
        #pragma unroll
        for (int j = 0; j < 8; j++)
            #pragma unroll
            for (int v = 0; v < 4; v++) c[i][j][v] = 0.0f;

    int sm  = tid >> 3;
    int sk4 = (tid & 7) * 4;
    uint32_t aArow = (uint32_t)(wm * 32 + (lane & 7) + ((lane >> 3) & 1) * 8);
    uint32_t aAseg = (uint32_t)(lane >> 4);
    uint32_t aBrow = (uint32_t)(wn * 64 + (lane >> 3) * 8 + (lane & 7));

    for (int k0 = 0; k0 < 256; k0 += 32) {
        __syncthreads();
        int hcol = (k0 + sk4) >> 5;
        #pragma unroll
        for (int it = 0; it < 4; it++) {
            int r = row0 + sm + it * 32;             // global attn row
            const float* ml0 = &mlpart[(size_t)r * (H_ * 2) + hcol * 2];
            const float* ml1 = ml0 + (size_t)B_ * LQ_ * H_ * 2;
            float m0 = ml0[0], l0 = ml0[1], m1 = ml1[0], l1 = ml1[1];
            float M = fmaxf(m0, m1);
            float w0 = ex2(m0 - M), w1 = ex2(m1 - M);
            float inv = 1.0f / (l0 * w0 + l1 * w1);
            w0 *= inv; w1 *= inv;
            float4 a0 = *(const float4*)&opart[(size_t)r * 256 + k0 + sk4];
            float4 a1 = *(const float4*)&opart[(size_t)(B_ * LQ_ + r) * 256 + k0 + sk4];
            float ax = a0.x * w0 + a1.x * w1;
            float ay = a0.y * w0 + a1.y * w1;
            float az = a0.z * w0 + a1.z * w1;
            float aw = a0.w * w0 + a1.w * w1;
            float4 w4 = *(const float4*)&W[(size_t)(col0 + sm + it * 32) * 256 + k0 + sk4];
            uint2 ua; ua.x = h2u(__floats2half2_rn(ax, ay)); ua.y = h2u(__floats2half2_rn(az, aw));
            uint2 uw; uw.x = h2u(__floats2half2_rn(w4.x, w4.y)); uw.y = h2u(__floats2half2_rn(w4.z, w4.w));
            *(uint2*)&As2[sm + it * 32][sk4 >> 1] = ua;
            *(uint2*)&Ws2[sm + it * 32][sk4 >> 1] = uw;
        }
        __syncthreads();
        #pragma unroll
        for (int kc = 0; kc < 2; kc++) {
            unsigned af0[4], af1[4];
            LDM_X4(af0, sbA + aArow * 80 + (kc * 2 + aAseg) * 16);
            LDM_X4(af1, sbA + (aArow + 16) * 80 + (kc * 2 + aAseg) * 16);
            unsigned b0a[4], b1a[4], b0b[4], b1b[4];
            uint32_t aB = sbW + aBrow * 80 + kc * 32;
            LDM_X4(b0a, aB);
            LDM_X4(b1a, aB + 16);
            LDM_X4(b0b, aB + 32 * 80);
            LDM_X4(b1b, aB + 32 * 80 + 16);
            #pragma unroll
            for (int j = 0; j < 8; j++) {
                unsigned bb0 = (j < 4) ? b0a[j] : b0b[j - 4];
                unsigned bb1 = (j < 4) ? b1a[j] : b1b[j - 4];
                mma_f16(c[0][j], af0, bb0, bb1);
                mma_f16(c[1][j], af1, bb0, bb1);
            }
        }
    }

    #pragma unroll
    for (int j = 0; j < 8; j++) {
        int colg = col0 + wn * 64 + j * 8 + 2 * tig;
        float2 bv = *(const float2*)&bias[colg];
        #pragma unroll
        for (int i = 0; i < 2; i++) {
            int rowg = row0 + wm * 32 + i * 16 + g;
            float2 r0, r1;
            r0.x = c[i][j][0] + bv.x; r0.y = c[i][j][1] + bv.y;
            r1.x = c[i][j][2] + bv.x; r1.y = c[i][j][3] + bv.y;
            *(float2*)&outp[(size_t)rowg * 256 + colg] = r0;
            *(float2*)&outp[(size_t)(rowg + 8) * 256 + colg] = r1;
        }
    }
}

// ---------------- flash attention ----------------
// grid (Lq/64, H, B*NSPLIT), 128 threads (4 warps). warp = (qg, kh): 32q x 32k-half.
__global__ void __launch_bounds__(128, 4) attn16(const __half* __restrict__ Qh,
                                                 const __half* __restrict__ KVh,
                                                 const __half* __restrict__ emh,
                                                 const float* __restrict__ farc,
                                                 float* __restrict__ opart,
                                                 float* __restrict__ mlpart) {
    __shared__ __align__(16) char KVM[2][STG_SZ];

    int tid = threadIdx.x;
    int lane = tid & 31, warp = tid >> 5;
    int qg = warp >> 1, kh = warp & 1;
    int g = lane >> 2, tig = lane & 3;
    int q0 = blockIdx.x * 64, h = blockIdx.y;
    int b = blockIdx.z >> 1, s = blockIdx.z & 1;
    int tb = s * TSPLIT;
    uint32_t sb = smem_u32(&KVM[0][0]);

    float tauMin = (float)q0 * STEPF;
    float tauMax = (float)(q0 + 63) * STEPF;
    int ttA = (int)floorf((tauMin - 448.0f - 63.0f - (float)tb) * (1.0f / 64.0f)) + 1;
    int ttB = (int)ceilf((tauMax + 448.0f - (float)tb) * (1.0f / 64.0f));
    ttA = max(0, min(NTILES, ttA));
    ttB = max(ttA, min(NTILES, ttB));
    float fL = farc[0], fR = farc[1];

    unsigned qf[2][2][4];
    #pragma unroll
    for (int mfr = 0; mfr < 2; mfr++) {
        const __half* qb0 = &Qh[(size_t)(b * LQ_ + q0 + qg * 32 + mfr * 16 + g) * DIM_ + h * HD_ + 2 * tig];
        #pragma unroll
        for (int kc = 0; kc < 2; kc++) {
            const __half* qb = qb0 + kc * 16;
            qf[mfr][kc][0] = *(const unsigned*)qb;
            qf[mfr][kc][1] = *(const unsigned*)(qb + 8 * DIM_);
            qf[mfr][kc][2] = *(const unsigned*)(qb + 8);
            qf[mfr][kc][3] = *(const unsigned*)(qb + 8 * DIM_ + 8);
        }
    }

    int srow = tid >> 2, seg = tid & 3;
    uint32_t dK0 = sb + (uint32_t)(srow * 80 + seg * 16);
    uint32_t dK1 = dK0 + 32 * 80;
    const __half* sKV = &KVh[(size_t)(b * T_ + tb + srow) * (2 * DIM_) + h * HD_ + seg * 8];
    int mrow = tid >> 1, mseg = (tid & 1) * 64;
    uint32_t dM = sb + OFF_M + (uint32_t)(mrow * 144 + mseg);
    const __half* sM = &emh[(size_t)(q0 + mrow) * T_ + tb + mseg / 2];

    uint32_t kAddr = (uint32_t)((kh * 32 + (lane >> 3) * 8 + (lane & 7)) * 80);
    uint32_t vAddr = (uint32_t)(OFF_V + (kh * 32 + (lane & 7)) * 80 + (lane >> 3) * 16);
    uint32_t mAddrB = (uint32_t)(OFF_M + (qg * 32 + (lane & 15)) * 144 + kh * 64 + (lane >> 4) * 16);

    unsigned bbone = (g == 0) ? 0x3C003C00u : 0u;

    float m[2][2], o[2][5][4];
    #pragma unroll
    for (int i = 0; i < 2; i++)
        #pragma unroll
        for (int j = 0; j < 2; j++) m[i][j] = -1e30f;
    #pragma unroll
    for (int i = 0; i < 2; i++)
        #pragma unroll
        for (int n = 0; n < 5; n++)
            #pragma unroll
            for (int v = 0; v < 4; v++) o[i][n][v] = 0.0f;

    {
        const __half* p = sKV;
        CP16(dK0, p); CP16(dK1, p + (size_t)32 * 2 * DIM_);
        CP16(dK0 + OFF_V, p + DIM_); CP16(dK1 + OFF_V, p + (size_t)32 * 2 * DIM_ + DIM_);
        if (0 >= ttA && 0 < ttB) {
            const __half* pm = sM;
            CP16(dM, pm); CP16(dM + 16, pm + 8); CP16(dM + 32, pm + 16); CP16(dM + 48, pm + 24);
        }
        CP_COMMIT();
    }

    for (int tt = 0; tt < NTILES; tt++) {
        uint32_t stoff = (uint32_t)((tt & 1) * STG_SZ);
        bool mixed = (tt >= ttA) && (tt < ttB);
        CP_WAIT0();
        __syncthreads();

        if (tt + 1 < NTILES) {
            uint32_t dst = (uint32_t)(((tt & 1) ^ 1) * STG_SZ);
            const __half* p = sKV + (size_t)(tt + 1) * 64 * 2 * DIM_;
            CP16(dK0 + dst, p); CP16(dK1 + dst, p + (size_t)32 * 2 * DIM_);
            CP16(dK0 + dst + OFF_V, p + DIM_); CP16(dK1 + dst + OFF_V, p + (size_t)32 * 2 * DIM_ + DIM_);
            if (tt + 1 >= ttA && tt + 1 < ttB) {
                const __half* pm = sM + (size_t)(tt + 1) * 64;
                uint32_t dMd = dM + dst;
                CP16(dMd, pm); CP16(dMd + 16, pm + 8); CP16(dMd + 32, pm + 16); CP16(dMd + 48, pm + 24);
            }
            CP_COMMIT();
        }

        // S = Q.K^T
        float c[2][4][4];
        #pragma unroll
        for (int mfr = 0; mfr < 2; mfr++)
            #pragma unroll
            for (int j = 0; j < 4; j++)
                #pragma unroll
                for (int v = 0; v < 4; v++) c[mfr][j][v] = 0.0f;
        #pragma unroll
        for (int kc = 0; kc < 2; kc++) {
            unsigned kb0[4], kb1[4];
            uint32_t aB = sb + stoff + kAddr + kc * 32;
            LDM_X4(kb0, aB);
            LDM_X4(kb1, aB + 16);
            #pragma unroll
            for (int j = 0; j < 4; j++) {
                mma_f16(c[0][j], qf[0][kc], kb0[j], kb1[j]);
                mma_f16(c[1][j], qf[1][kc], kb0[j], kb1[j]);
            }
        }

        // per-warp row max
        float mold[2][2];
        bool upd = false;
        #pragma unroll
        for (int mfr = 0; mfr < 2; mfr++)
            #pragma unroll
            for (int hi = 0; hi < 2; hi++) {
                float mx = fmaxf(c[mfr][0][hi * 2], c[mfr][0][hi * 2 + 1]);
                #pragma unroll
                for (int j = 1; j < 4; j++)
                    mx = fmaxf(mx, fmaxf(c[mfr][j][hi * 2], c[mfr][j][hi * 2 + 1]));
                mx = fmaxf(mx, __shfl_xor_sync(0xffffffffu, mx, 1));
                mx = fmaxf(mx, __shfl_xor_sync(0xffffffffu, mx, 2));
                mold[mfr][hi] = m[mfr][hi];
                float mn = fmaxf(m[mfr][hi], mx);
                upd |= (mn > m[mfr][hi]);
                m[mfr][hi] = mn;
            }

        if (__ballot_sync(0xffffffffu, upd)) {
            #pragma unroll
            for (int mfr = 0; mfr < 2; mfr++) {
                float a0 = ex2(mold[mfr][0] - m[mfr][0]);
                float a1 = ex2(mold[mfr][1] - m[mfr][1]);
                #pragma unroll
                for (int n = 0; n < 5; n++) {
                    o[mfr][n][0] *= a0; o[mfr][n][1] *= a0;
                    o[mfr][n][2] *= a1; o[mfr][n][3] *= a1;
                }
            }
        }

        // p fragments
        unsigned pf[2][2][4];
        if (mixed) {
            #pragma unroll
            for (int mfr = 0; mfr < 2; mfr++) {
                unsigned me0[4], me1[4];
                uint32_t aM = sb + stoff + mAddrB + (uint32_t)(mfr * 16 * 144);
                LDM_X4(me0, aM);
                LDM_X4(me1, aM + 32);
                #pragma unroll
                for (int j = 0; j < 4; j++) {
                    unsigned eg  = (j < 2) ? me0[(j & 1) * 2]     : me1[(j & 1) * 2];
                    unsigned eg8 = (j < 2) ? me0[(j & 1) * 2 + 1] : me1[(j & 1) * 2 + 1];
                    float2 ef0 = __half22float2(*(__half2*)&eg);
                    float2 ef1 = __half22float2(*(__half2*)&eg8);
                    float p0 = ex2(c[mfr][j][0] - m[mfr][0]) * ef0.x;
                    float p1 = ex2(c[mfr][j][1] - m[mfr][0]) * ef0.y;
                    float p2 = ex2(c[mfr][j][2] - m[mfr][1]) * ef1.x;
                    float p3 = ex2(c[mfr][j][3] - m[mfr][1]) * ef1.y;
                    pf[mfr][j >> 1][(j & 1) * 2 + 0] = h2u(__floats2half2_rn(p0, p1));
                    pf[mfr][j >> 1][(j & 1) * 2 + 1] = h2u(__floats2half2_rn(p2, p3));
                }
            }
        } else {
            // far tile: d = s - (m - flc) <= flc ~ -10 → p tiny; fp16 ex2 is exact enough
            float flc = (tt < ttA) ? fL : fR;
            #pragma unroll
            for (int mfr = 0; mfr < 2; mfr++) {
                float sh0 = m[mfr][0] - flc;
                float sh1 = m[mfr][1] - flc;
                #pragma unroll
                for (int j = 0; j < 4; j++) {
                    __half2 d0 = __floats2half2_rn(c[mfr][j][0] - sh0, c[mfr][j][1] - sh0);
                    __half2 d1 = __floats2half2_rn(c[mfr][j][2] - sh1, c[mfr][j][3] - sh1);
                    pf[mfr][j >> 1][(j & 1) * 2 + 0] = ex2h2(h2u(d0));
                    pf[mfr][j >> 1][(j & 1) * 2 + 1] = ex2h2(h2u(d1));
                }
            }
        }

        // O += P.V ; row sums via ones-column
        #pragma unroll
        for (int kc = 0; kc < 2; kc++) {
            unsigned vb0[4], vb1[4];
            uint32_t aV = sb + stoff + vAddr + (uint32_t)(kc * 16 * 80);
            LDM_X4T(vb0, aV);
            LDM_X4T(vb1, aV + 8 * 80);
            #pragma unroll
            for (int n = 0; n < 4; n++) {
                mma_f16(o[0][n], pf[0][kc], vb0[n], vb1[n]);
                mma_f16(o[1][n], pf[1][kc], vb0[n], vb1[n]);
            }
            mma_f16(o[0][4], pf[0][kc], bbone, bbone);
            mma_f16(o[1][4], pf[1][kc], bbone, bbone);
        }
    }

    __syncthreads();

    // combine kh halves with alpha weights (stride 42; m at col 40)
    float* Os = (float*)&KVM[0][0];
    if (kh == 1) {
        #pragma unroll
        for (int mfr = 0; mfr < 2; mfr++) {
            int r0 = qg * 1344 + (mfr * 16 + g) * 42;
            int r1 = r0 + 8 * 42;
            #pragma unroll
            for (int n = 0; n < 5; n++) {
                float2 w0; w0.x = o[mfr][n][0]; w0.y = o[mfr][n][1];
                float2 w1; w1.x = o[mfr][n][2]; w1.y = o[mfr][n][3];
                *(float2*)&Os[r0 + n * 8 + 2 * tig] = w0;
                *(float2*)&Os[r1 + n * 8 + 2 * tig] = w1;
            }
            if (tig == 0) {
                Os[r0 + 40] = m[mfr][0];
                Os[r1 + 40] = m[mfr][1];
            }
        }
    }
    __syncthreads();
    if (kh == 0) {
        #pragma unroll
        for (int mfr = 0; mfr < 2; mfr++) {
            int r0 = qg * 1344 + (mfr * 16 + g) * 42;
            int r1 = r0 + 8 * 42;
            float mo0 = Os[r0 + 40], mo1 = Os[r1 + 40];
            float M0 = fmaxf(m[mfr][0], mo0);
            float M1 = fmaxf(m[mfr][1], mo1);
            float ws0 = ex2(m[mfr][0] - M0), wo0 = ex2(mo0 - M0);
            float ws1 = ex2(m[mfr][1] - M1), wo1 = ex2(mo1 - M1);
            #pragma unroll
            for (int n = 0; n < 4; n++) {
                float2 p0 = *(float2*)&Os[r0 + n * 8 + 2 * tig];
                float2 p1 = *(float2*)&Os[r1 + n * 8 + 2 * tig];
                float2 w0, w1;
                w0.x = o[mfr][n][0] * ws0 + p0.x * wo0;
                w0.y = o[mfr][n][1] * ws0 + p0.y * wo0;
                w1.x = o[mfr][n][2] * ws1 + p1.x * wo1;
                w1.y = o[mfr][n][3] * ws1 + p1.y * wo1;
                int rg = (s * B_ + b) * LQ_ + q0 + qg * 32 + mfr * 16 + g;
                int col = h * HD_ + n * 8 + 2 * tig;
                *(float2*)&opart[(size_t)rg * DIM_ + col] = w0;
                *(float2*)&opart[(size_t)(rg + 8) * DIM_ + col] = w1;
            }
            if (tig == 0) {
                float l0 = o[mfr][4][0] * ws0 + Os[r0 + 32] * wo0;
                float l1 = o[mfr][4][2] * ws1 + Os[r1 + 32] * wo1;
                int rg = (s * B_ + b) * LQ_ + q0 + qg * 32 + mfr * 16 + g;
                float* mlb0 = &mlpart[(size_t)rg * (H_ * 2) + h * 2];
                float* mlb1 = &mlpart[(size_t)(rg + 8) * (H_ * 2) + h * 2];
                mlb0[0] = M0; mlb0[1] = l0;
                mlb1[0] = M1; mlb1[1] = l1;
            }
        }
    }
}

// ---------------- launch ----------------
extern "C" void kernel_launch(void* const* d_in, const int* in_sizes, int n_in,
                              void* d_out, int out_size) {
    const float* q          = (const float*)d_in[0];
    const float* kv         = (const float*)d_in[1];
    const float* in_proj_w  = (const float*)d_in[2];
    const float* in_proj_b  = (const float*)d_in[3];
    const float* out_proj_w = (const float*)d_in[4];
    const float* out_proj_b = (const float*)d_in[5];
    const float* rel_bias   = (const float*)d_in[6];
    const float* mask_scale = (const float*)d_in[7];
    float* out = (float*)d_out;

    __half *pQ, *pKV, *pEM;
    float *pOP, *pML, *pF;
    cudaGetSymbolAddress((void**)&pQ,  g_Qh);
    cudaGetSymbolAddress((void**)&pKV, g_KVh);
    cudaGetSymbolAddress((void**)&pEM, g_em);
    cudaGetSymbolAddress((void**)&pOP, g_op);
    cudaGetSymbolAddress((void**)&pML, g_ml);
    cudaGetSymbolAddress((void**)&pF,  g_far);

    const float attn_scale = 0.17677669529663687f * 1.4426950408889634f;

    emask_kernel<<<(LQ_ * T_) / 256, 256>>>(rel_bias, mask_scale, pEM, pF);

    // grid: x = col tiles, y = row tiles (A-tile reuse across x in L2)
    gemm16<<<dim3(DIM_ / 128, (B_ * LQ_) / 128), 256>>>(
        q, in_proj_w, in_proj_b, pQ, DIM_, attn_scale);

    gemm16<<<dim3((2 * DIM_) / 128, (B_ * T_) / 128), 256>>>(
        kv, in_proj_w + DIM_ * DIM_, in_proj_b + DIM_, pKV, 2 * DIM_, 1.0f);

    attn16<<<dim3(LQ_ / 64, H_, B_ * NSPLIT), 128>>>(pQ, pKV, pEM, pF, pOP, pML);

    gemm_out<<<dim3(DIM_ / 128, (B_ * LQ_) / 128), 256>>>(
        pOP, pML, out_proj_w, out_proj_b, out);
}

// round 15
// speedup vs baseline: 1.0389x; 1.0389x over previous
#include <cuda_runtime.h>
#include <cuda_fp16.h>
#include <math.h>
#include <stdint.h>

#define B_    8
#define H_    8
#define LQ_   512
#define T_    8192
#define DIM_  256
#define HD_   32
#define MAXREL_ 128
#define NSPLIT 2
#define TSPLIT (T_ / NSPLIT)
#define NTILES (TSPLIT / 64)
#define STEPF (8191.0f / 511.0f)

// ---------------- scratch ----------------
__device__ __half g_Qh[B_ * LQ_ * DIM_];
__device__ __half g_KVh[B_ * T_ * 2 * DIM_];
__device__ __half g_em[LQ_ * T_];
__device__ float  g_ctx[B_ * LQ_ * DIM_];
__device__ float  g_op[NSPLIT * B_ * LQ_ * DIM_];
__device__ float  g_ml[NSPLIT * B_ * LQ_ * H_ * 2];
__device__ float  g_far[2];

// ---------------- helpers ----------------
__device__ __forceinline__ void mma_f16(float c[4], const unsigned a[4], unsigned b0, unsigned b1) {
    asm volatile("mma.sync.aligned.m16n8k16.row.col.f32.f16.f16.f32 "
        "{%0,%1,%2,%3}, {%4,%5,%6,%7}, {%8,%9}, {%0,%1,%2,%3};"
        : "+f"(c[0]), "+f"(c[1]), "+f"(c[2]), "+f"(c[3])
        : "r"(a[0]), "r"(a[1]), "r"(a[2]), "r"(a[3]), "r"(b0), "r"(b1));
}
__device__ __forceinline__ unsigned h2u(__half2 h) { return *(unsigned*)&h; }
__device__ __forceinline__ uint32_t smem_u32(const void* p) {
    uint32_t a;
    asm("{ .reg .u64 t; cvta.to.shared.u64 t, %1; cvt.u32.u64 %0, t; }" : "=r"(a) : "l"(p));
    return a;
}
__device__ __forceinline__ float ex2(float x) {
    float r; asm("ex2.approx.f32 %0, %1;" : "=f"(r) : "f"(x)); return r;
}
__device__ __forceinline__ unsigned ex2h2(unsigned x) {
    unsigned r; asm("ex2.approx.f16x2 %0, %1;" : "=r"(r) : "r"(x)); return r;
}
#define LDM_X4(r, addr) \
    asm volatile("ldmatrix.sync.aligned.m8n8.x4.shared.b16 {%0,%1,%2,%3}, [%4];" \
        : "=r"((r)[0]), "=r"((r)[1]), "=r"((r)[2]), "=r"((r)[3]) : "r"(addr))
#define LDM_X4T(r, addr) \
    asm volatile("ldmatrix.sync.aligned.m8n8.x4.trans.shared.b16 {%0,%1,%2,%3}, [%4];" \
        : "=r"((r)[0]), "=r"((r)[1]), "=r"((r)[2]), "=r"((r)[3]) : "r"(addr))
#define CP16(dst, src) \
    asm volatile("cp.async.ca.shared.global [%0], [%1], 16;" :: "r"(dst), "l"(src))
#define CP_COMMIT() asm volatile("cp.async.commit_group;" ::: "memory")
#define CP_WAIT0()  asm volatile("cp.async.wait_group 0;" ::: "memory")

#define STG_SZ 19456
#define OFF_V  5120
#define OFF_M  10240

// ---------------- exp(mask) precompute (band-restricted) + far constants ----------------
__global__ void emask_kernel(const float* __restrict__ rel_bias,
                             const float* __restrict__ mask_scale,
                             __half* __restrict__ em,
                             float* __restrict__ farc) {
    int idx = blockIdx.x * blockDim.x + threadIdx.x;
    if (idx == 0) {
        const float L2E = 1.4426950408889634f;
        float ms = mask_scale[0];
        farc[0] = ms * (rel_bias[0] + __logf(1e-6f)) * L2E;
        farc[1] = ms * (rel_bias[2 * MAXREL_] + __logf(1e-6f)) * L2E;
    }
    int i = idx >> 13;
    int t = idx & (T_ - 1);
    float tau = (float)i * STEPF;
    float dt  = (float)t - tau;
    if (fabsf(dt) > 1664.0f) return;      // never read by any mixed tile
    float dtc = fminf(fmaxf(dt, -(float)MAXREL_), (float)MAXREL_);
    int bi = (int)dtc + MAXREL_;
    float bias = rel_bias[bi];
    float z = dt * (1.0f / 64.0f);
    float lg = __logf(__expf(-0.5f * z * z) + 1e-6f);
    em[idx] = __float2half_rn(__expf(mask_scale[0] * (bias + lg)));
}

// ---------------- fp16 GEMM (col tile on blockIdx.x for L2 A-reuse) ----------------
template<bool OHALF>
__global__ void __launch_bounds__(256, 2) gemm16(const float* __restrict__ A,
                                                 const float* __restrict__ W,
                                                 const float* __restrict__ bias,
                                                 void* __restrict__ outp,
                                                 int ldo, float scale) {
    __shared__ __align__(16) unsigned As2[128][20];
    __shared__ __align__(16) unsigned Ws2[128][20];
    int tid = threadIdx.x;
    int lane = tid & 31, warp = tid >> 5;
    int wm = warp >> 1, wn = warp & 1;
    int g = lane >> 2, tig = lane & 3;
    int row0 = blockIdx.y * 128, col0 = blockIdx.x * 128;
    uint32_t sbA = smem_u32(&As2[0][0]);
    uint32_t sbW = smem_u32(&Ws2[0][0]);

    float c[2][8][4];
    #pragma unroll
    for (int i = 0; i < 2; i++)
        #pragma unroll
        for (int j = 0; j < 8; j++)
            #pragma unroll
            for (int v = 0; v < 4; v++) c[i][j][v] = 0.0f;

    int sm  = tid >> 3;
    int sk4 = (tid & 7) * 4;
    uint32_t aArow = (uint32_t)(wm * 32 + (lane & 7) + ((lane >> 3) & 1) * 8);
    uint32_t aAseg = (uint32_t)(lane >> 4);
    uint32_t aBrow = (uint32_t)(wn * 64 + (lane >> 3) * 8 + (lane & 7));

    for (int k0 = 0; k0 < 256; k0 += 32) {
        __syncthreads();
        #pragma unroll
        for (int it = 0; it < 4; it++) {
            int r = sm + it * 32;
            float4 a4 = *(const float4*)&A[(size_t)(row0 + r) * 256 + k0 + sk4];
            float4 w4 = *(const float4*)&W[(size_t)(col0 + r) * 256 + k0 + sk4];
            uint2 ua; ua.x = h2u(__floats2half2_rn(a4.x, a4.y)); ua.y = h2u(__floats2half2_rn(a4.z, a4.w));
            uint2 uw; uw.x = h2u(__floats2half2_rn(w4.x, w4.y)); uw.y = h2u(__floats2half2_rn(w4.z, w4.w));
            *(uint2*)&As2[r][sk4 >> 1] = ua;
            *(uint2*)&Ws2[r][sk4 >> 1] = uw;
        }
        __syncthreads();
        #pragma unroll
        for (int kc = 0; kc < 2; kc++) {
            unsigned af0[4], af1[4];
            LDM_X4(af0, sbA + aArow * 80 + (kc * 2 + aAseg) * 16);
            LDM_X4(af1, sbA + (aArow + 16) * 80 + (kc * 2 + aAseg) * 16);
            unsigned b0a[4], b1a[4], b0b[4], b1b[4];
            uint32_t aB = sbW + aBrow * 80 + kc * 32;
            LDM_X4(b0a, aB);
            LDM_X4(b1a, aB + 16);
            LDM_X4(b0b, aB + 32 * 80);
            LDM_X4(b1b, aB + 32 * 80 + 16);
            #pragma unroll
            for (int j = 0; j < 8; j++) {
                unsigned bb0 = (j < 4) ? b0a[j] : b0b[j - 4];
                unsigned bb1 = (j < 4) ? b1a[j] : b1b[j - 4];
                mma_f16(c[0][j], af0, bb0, bb1);
                mma_f16(c[1][j], af1, bb0, bb1);
            }
        }
    }

    #pragma unroll
    for (int j = 0; j < 8; j++) {
        int colg = col0 + wn * 64 + j * 8 + 2 * tig;
        float2 bv = *(const float2*)&bias[colg];
        #pragma unroll
        for (int i = 0; i < 2; i++) {
            int rowg = row0 + wm * 32 + i * 16 + g;
            float x0 = scale * (c[i][j][0] + bv.x);
            float y0 = scale * (c[i][j][1] + bv.y);
            float x1 = scale * (c[i][j][2] + bv.x);
            float y1 = scale * (c[i][j][3] + bv.y);
            if (OHALF) {
                __half* o = (__half*)outp;
                *(unsigned*)&o[(size_t)rowg * ldo + colg] = h2u(__floats2half2_rn(x0, y0));
                *(unsigned*)&o[(size_t)(rowg + 8) * ldo + colg] = h2u(__floats2half2_rn(x1, y1));
            } else {
                float* o = (float*)outp;
                float2 r0; r0.x = x0; r0.y = y0;
                float2 r1; r1.x = x1; r1.y = y1;
                *(float2*)&o[(size_t)rowg * ldo + colg] = r0;
                *(float2*)&o[(size_t)(rowg + 8) * ldo + colg] = r1;
            }
        }
    }
}

// ---------------- flash attention (R13 version, measured 160.6us) ----------------
__global__ void __launch_bounds__(128, 4) attn16(const __half* __restrict__ Qh,
                                                 const __half* __restrict__ KVh,
                                                 const __half* __restrict__ emh,
                                                 const float* __restrict__ farc,
                                                 float* __restrict__ opart,
                                                 float* __restrict__ mlpart) {
    __shared__ __align__(16) char KVM[2][STG_SZ];

    int tid = threadIdx.x;
    int lane = tid & 31, warp = tid >> 5;
    int qg = warp >> 1, kh = warp & 1;
    int g = lane >> 2, tig = lane & 3;
    int q0 = blockIdx.x * 64, h = blockIdx.y;
    int b = blockIdx.z >> 1, s = blockIdx.z & 1;
    int tb = s * TSPLIT;
    uint32_t sb = smem_u32(&KVM[0][0]);

    float tauMin = (float)q0 * STEPF;
    float tauMax = (float)(q0 + 63) * STEPF;
    int ttA = (int)floorf((tauMin - 448.0f - 63.0f - (float)tb) * (1.0f / 64.0f)) + 1;
    int ttB = (int)ceilf((tauMax + 448.0f - (float)tb) * (1.0f / 64.0f));
    ttA = max(0, min(NTILES, ttA));
    ttB = max(ttA, min(NTILES, ttB));
    float fL = farc[0], fR = farc[1];

    unsigned qf[2][2][4];
    #pragma unroll
    for (int mfr = 0; mfr < 2; mfr++) {
        const __half* qb0 = &Qh[(size_t)(b * LQ_ + q0 + qg * 32 + mfr * 16 + g) * DIM_ + h * HD_ + 2 * tig];
        #pragma unroll
        for (int kc = 0; kc < 2; kc++) {
            const __half* qb = qb0 + kc * 16;
            qf[mfr][kc][0] = *(const unsigned*)qb;
            qf[mfr][kc][1] = *(const unsigned*)(qb + 8 * DIM_);
            qf[mfr][kc][2] = *(const unsigned*)(qb + 8);
            qf[mfr][kc][3] = *(const unsigned*)(qb + 8 * DIM_ + 8);
        }
    }

    int srow = tid >> 2, seg = tid & 3;
    uint32_t dK0 = sb + (uint32_t)(srow * 80 + seg * 16);
    uint32_t dK1 = dK0 + 32 * 80;
    const __half* sKV = &KVh[(size_t)(b * T_ + tb + srow) * (2 * DIM_) + h * HD_ + seg * 8];
    int mrow = tid >> 1, mseg = (tid & 1) * 64;
    uint32_t dM = sb + OFF_M + (uint32_t)(mrow * 144 + mseg);
    const __half* sM = &emh[(size_t)(q0 + mrow) * T_ + tb + mseg / 2];

    uint32_t kAddr = (uint32_t)((kh * 32 + (lane >> 3) * 8 + (lane & 7)) * 80);
    uint32_t vAddr = (uint32_t)(OFF_V + (kh * 32 + (lane & 7)) * 80 + (lane >> 3) * 16);
    uint32_t mAddrB = (uint32_t)(OFF_M + (qg * 32 + (lane & 15)) * 144 + kh * 64 + (lane >> 4) * 16);

    unsigned bbone = (g == 0) ? 0x3C003C00u : 0u;

    float m[2][2], o[2][5][4];
    #pragma unroll
    for (int i = 0; i < 2; i++)
        #pragma unroll
        for (int j = 0; j < 2; j++) m[i][j] = -1e30f;
    #pragma unroll
    for (int i = 0; i < 2; i++)
        #pragma unroll
        for (int n = 0; n < 5; n++)
            #pragma unroll
            for (int v = 0; v < 4; v++) o[i][n][v] = 0.0f;

    {
        const __half* p = sKV;
        CP16(dK0, p); CP16(dK1, p + (size_t)32 * 2 * DIM_);
        CP16(dK0 + OFF_V, p + DIM_); CP16(dK1 + OFF_V, p + (size_t)32 * 2 * DIM_ + DIM_);
        if (0 >= ttA && 0 < ttB) {
            const __half* pm = sM;
            CP16(dM, pm); CP16(dM + 16, pm + 8); CP16(dM + 32, pm + 16); CP16(dM + 48, pm + 24);
        }
        CP_COMMIT();
    }

    for (int tt = 0; tt < NTILES; tt++) {
        uint32_t stoff = (uint32_t)((tt & 1) * STG_SZ);
        bool mixed = (tt >= ttA) && (tt < ttB);
        CP_WAIT0();
        __syncthreads();

        if (tt + 1 < NTILES) {
            uint32_t dst = (uint32_t)(((tt & 1) ^ 1) * STG_SZ);
            const __half* p = sKV + (size_t)(tt + 1) * 64 * 2 * DIM_;
            CP16(dK0 + dst, p); CP16(dK1 + dst, p + (size_t)32 * 2 * DIM_);
            CP16(dK0 + dst + OFF_V, p + DIM_); CP16(dK1 + dst + OFF_V, p + (size_t)32 * 2 * DIM_ + DIM_);
            if (tt + 1 >= ttA && tt + 1 < ttB) {
                const __half* pm = sM + (size_t)(tt + 1) * 64;
                uint32_t dMd = dM + dst;
                CP16(dMd, pm); CP16(dMd + 16, pm + 8); CP16(dMd + 32, pm + 16); CP16(dMd + 48, pm + 24);
            }
            CP_COMMIT();
        }

        // S = Q.K^T
        float c[2][4][4];
        #pragma unroll
        for (int mfr = 0; mfr < 2; mfr++)
            #pragma unroll
            for (int j = 0; j < 4; j++)
                #pragma unroll
                for (int v = 0; v < 4; v++) c[mfr][j][v] = 0.0f;
        #pragma unroll
        for (int kc = 0; kc < 2; kc++) {
            unsigned kb0[4], kb1[4];
            uint32_t aB = sb + stoff + kAddr + kc * 32;
            LDM_X4(kb0, aB);
            LDM_X4(kb1, aB + 16);
            #pragma unroll
            for (int j = 0; j < 4; j++) {
                mma_f16(c[0][j], qf[0][kc], kb0[j], kb1[j]);
                mma_f16(c[1][j], qf[1][kc], kb0[j], kb1[j]);
            }
        }

        // per-warp row max
        float mold[2][2];
        bool upd = false;
        #pragma unroll
        for (int mfr = 0; mfr < 2; mfr++)
            #pragma unroll
            for (int hi = 0; hi < 2; hi++) {
                float mx = fmaxf(c[mfr][0][hi * 2], c[mfr][0][hi * 2 + 1]);
                #pragma unroll
                for (int j = 1; j < 4; j++)
                    mx = fmaxf(mx, fmaxf(c[mfr][j][hi * 2], c[mfr][j][hi * 2 + 1]));
                mx = fmaxf(mx, __shfl_xor_sync(0xffffffffu, mx, 1));
                mx = fmaxf(mx, __shfl_xor_sync(0xffffffffu, mx, 2));
                mold[mfr][hi] = m[mfr][hi];
                float mn = fmaxf(m[mfr][hi], mx);
                upd |= (mn > m[mfr][hi]);
                m[mfr][hi] = mn;
            }

        if (__ballot_sync(0xffffffffu, upd)) {
            #pragma unroll
            for (int mfr = 0; mfr < 2; mfr++) {
                float a0 = ex2(mold[mfr][0] - m[mfr][0]);
                float a1 = ex2(mold[mfr][1] - m[mfr][1]);
                #pragma unroll
                for (int n = 0; n < 5; n++) {
                    o[mfr][n][0] *= a0; o[mfr][n][1] *= a0;
                    o[mfr][n][2] *= a1; o[mfr][n][3] *= a1;
                }
            }
        }

        // p fragments
        unsigned pf[2][2][4];
        if (mixed) {
            #pragma unroll
            for (int mfr = 0; mfr < 2; mfr++) {
                unsigned me0[4], me1[4];
                uint32_t aM = sb + stoff + mAddrB + (uint32_t)(mfr * 16 * 144);
                LDM_X4(me0, aM);
                LDM_X4(me1, aM + 32);
                #pragma unroll
                for (int j = 0; j < 4; j++) {
                    unsigned eg  = (j < 2) ? me0[(j & 1) * 2]     : me1[(j & 1) * 2];
                    unsigned eg8 = (j < 2) ? me0[(j & 1) * 2 + 1] : me1[(j & 1) * 2 + 1];
                    float2 ef0 = __half22float2(*(__half2*)&eg);
                    float2 ef1 = __half22float2(*(__half2*)&eg8);
                    float p0 = ex2(c[mfr][j][0] - m[mfr][0]) * ef0.x;
                    float p1 = ex2(c[mfr][j][1] - m[mfr][0]) * ef0.y;
                    float p2 = ex2(c[mfr][j][2] - m[mfr][1]) * ef1.x;
                    float p3 = ex2(c[mfr][j][3] - m[mfr][1]) * ef1.y;
                    pf[mfr][j >> 1][(j & 1) * 2 + 0] = h2u(__floats2half2_rn(p0, p1));
                    pf[mfr][j >> 1][(j & 1) * 2 + 1] = h2u(__floats2half2_rn(p2, p3));
                }
            }
        } else {
            float flc = (tt < ttA) ? fL : fR;
            #pragma unroll
            for (int mfr = 0; mfr < 2; mfr++) {
                float sh0 = m[mfr][0] - flc;
                float sh1 = m[mfr][1] - flc;
                #pragma unroll
                for (int j = 0; j < 4; j++) {
                    __half2 d0 = __floats2half2_rn(c[mfr][j][0] - sh0, c[mfr][j][1] - sh0);
                    __half2 d1 = __floats2half2_rn(c[mfr][j][2] - sh1, c[mfr][j][3] - sh1);
                    pf[mfr][j >> 1][(j & 1) * 2 + 0] = ex2h2(h2u(d0));
                    pf[mfr][j >> 1][(j & 1) * 2 + 1] = ex2h2(h2u(d1));
                }
            }
        }

        // O += P.V ; row sums via ones-column
        #pragma unroll
        for (int kc = 0; kc < 2; kc++) {
            unsigned vb0[4], vb1[4];
            uint32_t aV = sb + stoff + vAddr + (uint32_t)(kc * 16 * 80);
            LDM_X4T(vb0, aV);
            LDM_X4T(vb1, aV + 8 * 80);
            #pragma unroll
            for (int n = 0; n < 4; n++) {
                mma_f16(o[0][n], pf[0][kc], vb0[n], vb1[n]);
                mma_f16(o[1][n], pf[1][kc], vb0[n], vb1[n]);
            }
            mma_f16(o[0][4], pf[0][kc], bbone, bbone);
            mma_f16(o[1][4], pf[1][kc], bbone, bbone);
        }
    }

    __syncthreads();

    // combine kh halves with alpha weights (stride 42; m at col 40)
    float* Os = (float*)&KVM[0][0];
    if (kh == 1) {
        #pragma unroll
        for (int mfr = 0; mfr < 2; mfr++) {
            int r0 = qg * 1344 + (mfr * 16 + g) * 42;
            int r1 = r0 + 8 * 42;
            #pragma unroll
            for (int n = 0; n < 5; n++) {
                float2 w0; w0.x = o[mfr][n][0]; w0.y = o[mfr][n][1];
                float2 w1; w1.x = o[mfr][n][2]; w1.y = o[mfr][n][3];
                *(float2*)&Os[r0 + n * 8 + 2 * tig] = w0;
                *(float2*)&Os[r1 + n * 8 + 2 * tig] = w1;
            }
            if (tig == 0) {
                Os[r0 + 40] = m[mfr][0];
                Os[r1 + 40] = m[mfr][1];
            }
        }
    }
    __syncthreads();
    if (kh == 0) {
        #pragma unroll
        for (int mfr = 0; mfr < 2; mfr++) {
            int r0 = qg * 1344 + (mfr * 16 + g) * 42;
            int r1 = r0 + 8 * 42;
            float mo0 = Os[r0 + 40], mo1 = Os[r1 + 40];
            float M0 = fmaxf(m[mfr][0], mo0);
            float M1 = fmaxf(m[mfr][1], mo1);
            float ws0 = ex2(m[mfr][0] - M0), wo0 = ex2(mo0 - M0);
            float ws1 = ex2(m[mfr][1] - M1), wo1 = ex2(mo1 - M1);
            #pragma unroll
            for (int n = 0; n < 4; n++) {
                float2 p0 = *(float2*)&Os[r0 + n * 8 + 2 * tig];
                float2 p1 = *(float2*)&Os[r1 + n * 8 + 2 * tig];
                float2 w0, w1;
                w0.x = o[mfr][n][0] * ws0 + p0.x * wo0;
                w0.y = o[mfr][n][1] * ws0 + p0.y * wo0;
                w1.x = o[mfr][n][2] * ws1 + p1.x * wo1;
                w1.y = o[mfr][n][3] * ws1 + p1.y * wo1;
                int rg = (s * B_ + b) * LQ_ + q0 + qg * 32 + mfr * 16 + g;
                int col = h * HD_ + n * 8 + 2 * tig;
                *(float2*)&opart[(size_t)rg * DIM_ + col] = w0;
                *(float2*)&opart[(size_t)(rg + 8) * DIM_ + col] = w1;
            }
            if (tig == 0) {
                float l0 = o[mfr][4][0] * ws0 + Os[r0 + 32] * wo0;
                float l1 = o[mfr][4][2] * ws1 + Os[r1 + 32] * wo1;
                int rg = (s * B_ + b) * LQ_ + q0 + qg * 32 + mfr * 16 + g;
                float* mlb0 = &mlpart[(size_t)rg * (H_ * 2) + h * 2];
                float* mlb1 = &mlpart[(size_t)(rg + 8) * (H_ * 2) + h * 2];
                mlb0[0] = M0; mlb0[1] = l0;
                mlb1[0] = M1; mlb1[1] = l1;
            }
        }
    }
}

// ---------------- split merge (m in log2 units) ----------------
__global__ void merge_kernel(const float* __restrict__ opart,
                             const float* __restrict__ mlpart,
                             float* __restrict__ ctx) {
    int idx = blockIdx.x * blockDim.x + threadIdx.x;
    int row = idx >> 6;
    int d4 = (idx & 63) * 4;
    int h = d4 >> 5;
    const float* ml0 = &mlpart[(size_t)row * (H_ * 2) + h * 2];
    const float* ml1 = ml0 + (size_t)B_ * LQ_ * H_ * 2;
    float m0 = ml0[0], l0 = ml0[1], m1 = ml1[0], l1 = ml1[1];
    float M = fmaxf(m0, m1);
    float w0 = ex2(m0 - M), w1 = ex2(m1 - M);
    float inv = 1.0f / (l0 * w0 + l1 * w1);
    float4 a = *(const float4*)&opart[(size_t)row * DIM_ + d4];
    float4 bb = *(const float4*)&opart[(size_t)(B_ * LQ_ + row) * DIM_ + d4];
    float4 r;
    r.x = (a.x * w0 + bb.x * w1) * inv;
    r.y = (a.y * w0 + bb.y * w1) * inv;
    r.z = (a.z * w0 + bb.z * w1) * inv;
    r.w = (a.w * w0 + bb.w * w1) * inv;
    *(float4*)&ctx[(size_t)row * DIM_ + d4] = r;
}

// ---------------- launch ----------------
extern "C" void kernel_launch(void* const* d_in, const int* in_sizes, int n_in,
                              void* d_out, int out_size) {
    const float* q          = (const float*)d_in[0];
    const float* kv         = (const float*)d_in[1];
    const float* in_proj_w  = (const float*)d_in[2];
    const float* in_proj_b  = (const float*)d_in[3];
    const float* out_proj_w = (const float*)d_in[4];
    const float* out_proj_b = (const float*)d_in[5];
    const float* rel_bias   = (const float*)d_in[6];
    const float* mask_scale = (const float*)d_in[7];
    float* out = (float*)d_out;

    __half *pQ, *pKV, *pEM;
    float *pC, *pOP, *pML, *pF;
    cudaGetSymbolAddress((void**)&pQ,  g_Qh);
    cudaGetSymbolAddress((void**)&pKV, g_KVh);
    cudaGetSymbolAddress((void**)&pEM, g_em);
    cudaGetSymbolAddress((void**)&pC,  g_ctx);
    cudaGetSymbolAddress((void**)&pOP, g_op);
    cudaGetSymbolAddress((void**)&pML, g_ml);
    cudaGetSymbolAddress((void**)&pF,  g_far);

    const float attn_scale = 0.17677669529663687f * 1.4426950408889634f;

    emask_kernel<<<(LQ_ * T_) / 256, 256>>>(rel_bias, mask_scale, pEM, pF);

    // grid: x = col tiles, y = row tiles (A-tile reuse across x in L2)
    gemm16<true><<<dim3(DIM_ / 128, (B_ * LQ_) / 128), 256>>>(
        q, in_proj_w, in_proj_b, pQ, DIM_, attn_scale);

    gemm16<true><<<dim3((2 * DIM_) / 128, (B_ * T_) / 128), 256>>>(
        kv, in_proj_w + DIM_ * DIM_, in_proj_b + DIM_, pKV, 2 * DIM_, 1.0f);

    attn16<<<dim3(LQ_ / 64, H_, B_ * NSPLIT), 128>>>(pQ, pKV, pEM, pF, pOP, pML);

    merge_kernel<<<(B_ * LQ_ * DIM_ / 4) / 256, 256>>>(pOP, pML, pC);

    gemm16<false><<<dim3(DIM_ / 128, (B_ * LQ_) / 128), 256>>>(
        pC, out_proj_w, out_proj_b, out, DIM_, 1.0f);
}

// round 16
// speedup vs baseline: 1.0635x; 1.0237x over previous
#include <cuda_runtime.h>
#include <cuda_fp16.h>
#include <math.h>
#include <stdint.h>

#define B_    8
#define H_    8
#define LQ_   512
#define T_    8192
#define DIM_  256
#define HD_   32
#define MAXREL_ 128
#define NSPLIT 2
#define TSPLIT (T_ / NSPLIT)
#define NTILES (TSPLIT / 64)
#define STEPF (8191.0f / 511.0f)

// ---------------- scratch ----------------
__device__ __half g_qx[B_ * LQ_ * DIM_];        // fp16 copy of q input
__device__ __half g_kvx[B_ * T_ * DIM_];        // fp16 copy of kv input
__device__ __half g_w16[3 * DIM_ * DIM_];       // fp16 in_proj_w
__device__ __half g_wo16[DIM_ * DIM_];          // fp16 out_proj_w
__device__ __half g_Qh[B_ * LQ_ * DIM_];
__device__ __half g_KVh[B_ * T_ * 2 * DIM_];
__device__ __half g_em[LQ_ * T_];
__device__ __half g_ctxh[B_ * LQ_ * DIM_];
__device__ float  g_op[NSPLIT * B_ * LQ_ * DIM_];
__device__ float  g_ml[NSPLIT * B_ * LQ_ * H_ * 2];
__device__ float  g_far[2];

// ---------------- helpers ----------------
__device__ __forceinline__ void mma_f16(float c[4], const unsigned a[4], unsigned b0, unsigned b1) {
    asm volatile("mma.sync.aligned.m16n8k16.row.col.f32.f16.f16.f32 "
        "{%0,%1,%2,%3}, {%4,%5,%6,%7}, {%8,%9}, {%0,%1,%2,%3};"
        : "+f"(c[0]), "+f"(c[1]), "+f"(c[2]), "+f"(c[3])
        : "r"(a[0]), "r"(a[1]), "r"(a[2]), "r"(a[3]), "r"(b0), "r"(b1));
}
__device__ __forceinline__ unsigned h2u(__half2 h) { return *(unsigned*)&h; }
__device__ __forceinline__ uint32_t smem_u32(const void* p) {
    uint32_t a;
    asm("{ .reg .u64 t; cvta.to.shared.u64 t, %1; cvt.u32.u64 %0, t; }" : "=r"(a) : "l"(p));
    return a;
}
__device__ __forceinline__ float ex2(float x) {
    float r; asm("ex2.approx.f32 %0, %1;" : "=f"(r) : "f"(x)); return r;
}
__device__ __forceinline__ unsigned ex2h2(unsigned x) {
    unsigned r; asm("ex2.approx.f16x2 %0, %1;" : "=r"(r) : "r"(x)); return r;
}
#define LDM_X4(r, addr) \
    asm volatile("ldmatrix.sync.aligned.m8n8.x4.shared.b16 {%0,%1,%2,%3}, [%4];" \
        : "=r"((r)[0]), "=r"((r)[1]), "=r"((r)[2]), "=r"((r)[3]) : "r"(addr))
#define LDM_X4T(r, addr) \
    asm volatile("ldmatrix.sync.aligned.m8n8.x4.trans.shared.b16 {%0,%1,%2,%3}, [%4];" \
        : "=r"((r)[0]), "=r"((r)[1]), "=r"((r)[2]), "=r"((r)[3]) : "r"(addr))
#define CP16(dst, src) \
    asm volatile("cp.async.ca.shared.global [%0], [%1], 16;" :: "r"(dst), "l"(src))
#define CP_COMMIT() asm volatile("cp.async.commit_group;" ::: "memory")
#define CP_WAIT0()  asm volatile("cp.async.wait_group 0;" ::: "memory")

#define STG_SZ 19456
#define OFF_V  5120
#define OFF_M  10240

// ---------------- fp32 -> fp16 conversion ----------------
__global__ void cvt16(const float* __restrict__ src, __half* __restrict__ dst) {
    int i = (blockIdx.x * blockDim.x + threadIdx.x) * 8;
    float4 a = *(const float4*)&src[i];
    float4 b = *(const float4*)&src[i + 4];
    uint4 u;
    u.x = h2u(__floats2half2_rn(a.x, a.y)); u.y = h2u(__floats2half2_rn(a.z, a.w));
    u.z = h2u(__floats2half2_rn(b.x, b.y)); u.w = h2u(__floats2half2_rn(b.z, b.w));
    *(uint4*)&dst[i] = u;
}

// ---------------- exp(mask) precompute (band-restricted) + far constants ----------------
__global__ void emask_kernel(const float* __restrict__ rel_bias,
                             const float* __restrict__ mask_scale,
                             __half* __restrict__ em,
                             float* __restrict__ farc) {
    int idx = blockIdx.x * blockDim.x + threadIdx.x;
    if (idx == 0) {
        const float L2E = 1.4426950408889634f;
        float ms = mask_scale[0];
        farc[0] = ms * (rel_bias[0] + __logf(1e-6f)) * L2E;
        farc[1] = ms * (rel_bias[2 * MAXREL_] + __logf(1e-6f)) * L2E;
    }
    int i = idx >> 13;
    int t = idx & (T_ - 1);
    float tau = (float)i * STEPF;
    float dt  = (float)t - tau;
    if (fabsf(dt) > 1664.0f) return;
    float dtc = fminf(fmaxf(dt, -(float)MAXREL_), (float)MAXREL_);
    int bi = (int)dtc + MAXREL_;
    float bias = rel_bias[bi];
    float z = dt * (1.0f / 64.0f);
    float lg = __logf(__expf(-0.5f * z * z) + 1e-6f);
    em[idx] = __float2half_rn(__expf(mask_scale[0] * (bias + lg)));
}

// ---------------- fp16-input GEMM, cp.async double-buffered ----------------
// A [M,256] fp16, W [N,256] fp16, bias fp32. Block tile 128x128, 8 warps (4m x 2n).
template<bool OHALF>
__global__ void __launch_bounds__(256, 2) gemm16h(const __half* __restrict__ A,
                                                  const __half* __restrict__ W,
                                                  const float* __restrict__ bias,
                                                  void* __restrict__ outp,
                                                  int ldo, float scale) {
    __shared__ __align__(16) char SB[2][2 * 10240];   // [stage][A(10240) | W(10240)], 80B rows
    int tid = threadIdx.x;
    int lane = tid & 31, warp = tid >> 5;
    int wm = warp >> 1, wn = warp & 1;
    int g = lane >> 2, tig = lane & 3;
    int row0 = blockIdx.y * 128, col0 = blockIdx.x * 128;
    uint32_t sb = smem_u32(&SB[0][0]);

    float c[2][8][4];
    #pragma unroll
    for (int i = 0; i < 2; i++)
        #pragma unroll
        for (int j = 0; j < 8; j++)
            #pragma unroll
            for (int v = 0; v < 4; v++) c[i][j][v] = 0.0f;

    // staging: thread covers rows r and r+64 for A and W (4 cp.async per chunk)
    int r = tid >> 2, seg = tid & 3;
    const __half* pA = A + (size_t)(row0 + r) * 256 + seg * 8;
    const __half* pW = W + (size_t)(col0 + r) * 256 + seg * 8;
    uint32_t dA = sb + (uint32_t)(r * 80 + seg * 16);
    uint32_t dW = dA + 10240;

    uint32_t aArow = (uint32_t)(wm * 32 + (lane & 7) + ((lane >> 3) & 1) * 8);
    uint32_t aAseg = (uint32_t)(lane >> 4);
    uint32_t aBrow = (uint32_t)(wn * 64 + (lane >> 3) * 8 + (lane & 7));

    // prologue: chunk 0 -> stage 0
    CP16(dA, pA); CP16(dA + 64 * 80, pA + 64 * 256);
    CP16(dW, pW); CP16(dW + 64 * 80, pW + 64 * 256);
    CP_COMMIT();

    #pragma unroll 1
    for (int kc8 = 0; kc8 < 8; kc8++) {
        CP_WAIT0();
        __syncthreads();
        if (kc8 + 1 < 8) {
            uint32_t dst = (uint32_t)(((kc8 & 1) ^ 1) * 20480);
            int k0 = (kc8 + 1) * 32;
            CP16(dA + dst, pA + k0); CP16(dA + dst + 64 * 80, pA + 64 * 256 + k0);
            CP16(dW + dst, pW + k0); CP16(dW + dst + 64 * 80, pW + 64 * 256 + k0);
            CP_COMMIT();
        }
        uint32_t sbA = sb + (uint32_t)((kc8 & 1) * 20480);
        uint32_t sbW = sbA + 10240;
        #pragma unroll
        for (int kc = 0; kc < 2; kc++) {
            unsigned af0[4], af1[4];
            LDM_X4(af0, sbA + aArow * 80 + (kc * 2 + aAseg) * 16);
            LDM_X4(af1, sbA + (aArow + 16) * 80 + (kc * 2 + aAseg) * 16);
            unsigned b0a[4], b1a[4], b0b[4], b1b[4];
            uint32_t aB = sbW + aBrow * 80 + kc * 32;
            LDM_X4(b0a, aB);
            LDM_X4(b1a, aB + 16);
            LDM_X4(b0b, aB + 32 * 80);
            LDM_X4(b1b, aB + 32 * 80 + 16);
            #pragma unroll
            for (int j = 0; j < 8; j++) {
                unsigned bb0 = (j < 4) ? b0a[j] : b0b[j - 4];
                unsigned bb1 = (j < 4) ? b1a[j] : b1b[j - 4];
                mma_f16(c[0][j], af0, bb0, bb1);
                mma_f16(c[1][j], af1, bb0, bb1);
            }
        }
        __syncthreads();     // compute done before next iteration's prefetch target reuse
    }

    #pragma unroll
    for (int j = 0; j < 8; j++) {
        int colg = col0 + wn * 64 + j * 8 + 2 * tig;
        float2 bv = *(const float2*)&bias[colg];
        #pragma unroll
        for (int i = 0; i < 2; i++) {
            int rowg = row0 + wm * 32 + i * 16 + g;
            float x0 = scale * (c[i][j][0] + bv.x);
            float y0 = scale * (c[i][j][1] + bv.y);
            float x1 = scale * (c[i][j][2] + bv.x);
            float y1 = scale * (c[i][j][3] + bv.y);
            if (OHALF) {
                __half* o = (__half*)outp;
                *(unsigned*)&o[(size_t)rowg * ldo + colg] = h2u(__floats2half2_rn(x0, y0));
                *(unsigned*)&o[(size_t)(rowg + 8) * ldo + colg] = h2u(__floats2half2_rn(x1, y1));
            } else {
                float* o = (float*)outp;
                float2 r0; r0.x = x0; r0.y = y0;
                float2 r1; r1.x = x1; r1.y = y1;
                *(float2*)&o[(size_t)rowg * ldo + colg] = r0;
                *(float2*)&o[(size_t)(rowg + 8) * ldo + colg] = r1;
            }
        }
    }
}

// ---------------- flash attention (R15 version, measured ~163us) ----------------
__global__ void __launch_bounds__(128, 4) attn16(const __half* __restrict__ Qh,
                                                 const __half* __restrict__ KVh,
                                                 const __half* __restrict__ emh,
                                                 const float* __restrict__ farc,
                                                 float* __restrict__ opart,
                                                 float* __restrict__ mlpart) {
    __shared__ __align__(16) char KVM[2][STG_SZ];

    int tid = threadIdx.x;
    int lane = tid & 31, warp = tid >> 5;
    int qg = warp >> 1, kh = warp & 1;
    int g = lane >> 2, tig = lane & 3;
    int q0 = blockIdx.x * 64, h = blockIdx.y;
    int b = blockIdx.z >> 1, s = blockIdx.z & 1;
    int tb = s * TSPLIT;
    uint32_t sb = smem_u32(&KVM[0][0]);

    float tauMin = (float)q0 * STEPF;
    float tauMax = (float)(q0 + 63) * STEPF;
    int ttA = (int)floorf((tauMin - 448.0f - 63.0f - (float)tb) * (1.0f / 64.0f)) + 1;
    int ttB = (int)ceilf((tauMax + 448.0f - (float)tb) * (1.0f / 64.0f));
    ttA = max(0, min(NTILES, ttA));
    ttB = max(ttA, min(NTILES, ttB));
    float fL = farc[0], fR = farc[1];

    unsigned qf[2][2][4];
    #pragma unroll
    for (int mfr = 0; mfr < 2; mfr++) {
        const __half* qb0 = &Qh[(size_t)(b * LQ_ + q0 + qg * 32 + mfr * 16 + g) * DIM_ + h * HD_ + 2 * tig];
        #pragma unroll
        for (int kc = 0; kc < 2; kc++) {
            const __half* qb = qb0 + kc * 16;
            qf[mfr][kc][0] = *(const unsigned*)qb;
            qf[mfr][kc][1] = *(const unsigned*)(qb + 8 * DIM_);
            qf[mfr][kc][2] = *(const unsigned*)(qb + 8);
            qf[mfr][kc][3] = *(const unsigned*)(qb + 8 * DIM_ + 8);
        }
    }

    int srow = tid >> 2, seg = tid & 3;
    uint32_t dK0 = sb + (uint32_t)(srow * 80 + seg * 16);
    uint32_t dK1 = dK0 + 32 * 80;
    const __half* sKV = &KVh[(size_t)(b * T_ + tb + srow) * (2 * DIM_) + h * HD_ + seg * 8];
    int mrow = tid >> 1, mseg = (tid & 1) * 64;
    uint32_t dM = sb + OFF_M + (uint32_t)(mrow * 144 + mseg);
    const __half* sM = &emh[(size_t)(q0 + mrow) * T_ + tb + mseg / 2];

    uint32_t kAddr = (uint32_t)((kh * 32 + (lane >> 3) * 8 + (lane & 7)) * 80);
    uint32_t vAddr = (uint32_t)(OFF_V + (kh * 32 + (lane & 7)) * 80 + (lane >> 3) * 16);
    uint32_t mAddrB = (uint32_t)(OFF_M + (qg * 32 + (lane & 15)) * 144 + kh * 64 + (lane >> 4) * 16);

    unsigned bbone = (g == 0) ? 0x3C003C00u : 0u;

    float m[2][2], o[2][5][4];
    #pragma unroll
    for (int i = 0; i < 2; i++)
        #pragma unroll
        for (int j = 0; j < 2; j++) m[i][j] = -1e30f;
    #pragma unroll
    for (int i = 0; i < 2; i++)
        #pragma unroll
        for (int n = 0; n < 5; n++)
            #pragma unroll
            for (int v = 0; v < 4; v++) o[i][n][v] = 0.0f;

    {
        const __half* p = sKV;
        CP16(dK0, p); CP16(dK1, p + (size_t)32 * 2 * DIM_);
        CP16(dK0 + OFF_V, p + DIM_); CP16(dK1 + OFF_V, p + (size_t)32 * 2 * DIM_ + DIM_);
        if (0 >= ttA && 0 < ttB) {
            const __half* pm = sM;
            CP16(dM, pm); CP16(dM + 16, pm + 8); CP16(dM + 32, pm + 16); CP16(dM + 48, pm + 24);
        }
        CP_COMMIT();
    }

    for (int tt = 0; tt < NTILES; tt++) {
        uint32_t stoff = (uint32_t)((tt & 1) * STG_SZ);
        bool mixed = (tt >= ttA) && (tt < ttB);
        CP_WAIT0();
        __syncthreads();

        if (tt + 1 < NTILES) {
            uint32_t dst = (uint32_t)(((tt & 1) ^ 1) * STG_SZ);
            const __half* p = sKV + (size_t)(tt + 1) * 64 * 2 * DIM_;
            CP16(dK0 + dst, p); CP16(dK1 + dst, p + (size_t)32 * 2 * DIM_);
            CP16(dK0 + dst + OFF_V, p + DIM_); CP16(dK1 + dst + OFF_V, p + (size_t)32 * 2 * DIM_ + DIM_);
            if (tt + 1 >= ttA && tt + 1 < ttB) {
                const __half* pm = sM + (size_t)(tt + 1) * 64;
                uint32_t dMd = dM + dst;
                CP16(dMd, pm); CP16(dMd + 16, pm + 8); CP16(dMd + 32, pm + 16); CP16(dMd + 48, pm + 24);
            }
            CP_COMMIT();
        }

        float c[2][4][4];
        #pragma unroll
        for (int mfr = 0; mfr < 2; mfr++)
            #pragma unroll
            for (int j = 0; j < 4; j++)
                #pragma unroll
                for (int v = 0; v < 4; v++) c[mfr][j][v] = 0.0f;
        #pragma unroll
        for (int kc = 0; kc < 2; kc++) {
            unsigned kb0[4], kb1[4];
            uint32_t aB = sb + stoff + kAddr + kc * 32;
            LDM_X4(kb0, aB);
            LDM_X4(kb1, aB + 16);
            #pragma unroll
            for (int j = 0; j < 4; j++) {
                mma_f16(c[0][j], qf[0][kc], kb0[j], kb1[j]);
                mma_f16(c[1][j], qf[1][kc], kb0[j], kb1[j]);
            }
        }

        float mold[2][2];
        bool upd = false;
        #pragma unroll
        for (int mfr = 0; mfr < 2; mfr++)
            #pragma unroll
            for (int hi = 0; hi < 2; hi++) {
                float mx = fmaxf(c[mfr][0][hi * 2], c[mfr][0][hi * 2 + 1]);
                #pragma unroll
                for (int j = 1; j < 4; j++)
                    mx = fmaxf(mx, fmaxf(c[mfr][j][hi * 2], c[mfr][j][hi * 2 + 1]));
                mx = fmaxf(mx, __shfl_xor_sync(0xffffffffu, mx, 1));
                mx = fmaxf(mx, __shfl_xor_sync(0xffffffffu, mx, 2));
                mold[mfr][hi] = m[mfr][hi];
                float mn = fmaxf(m[mfr][hi], mx);
                upd |= (mn > m[mfr][hi]);
                m[mfr][hi] = mn;
            }

        if (__ballot_sync(0xffffffffu, upd)) {
            #pragma unroll
            for (int mfr = 0; mfr < 2; mfr++) {
                float a0 = ex2(mold[mfr][0] - m[mfr][0]);
                float a1 = ex2(mold[mfr][1] - m[mfr][1]);
                #pragma unroll
                for (int n = 0; n < 5; n++) {
                    o[mfr][n][0] *= a0; o[mfr][n][1] *= a0;
                    o[mfr][n][2] *= a1; o[mfr][n][3] *= a1;
                }
            }
        }

        unsigned pf[2][2][4];
        if (mixed) {
            #pragma unroll
            for (int mfr = 0; mfr < 2; mfr++) {
                unsigned me0[4], me1[4];
                uint32_t aM = sb + stoff + mAddrB + (uint32_t)(mfr * 16 * 144);
                LDM_X4(me0, aM);
                LDM_X4(me1, aM + 32);
                #pragma unroll
                for (int j = 0; j < 4; j++) {
                    unsigned eg  = (j < 2) ? me0[(j & 1) * 2]     : me1[(j & 1) * 2];
                    unsigned eg8 = (j < 2) ? me0[(j & 1) * 2 + 1] : me1[(j & 1) * 2 + 1];
                    float2 ef0 = __half22float2(*(__half2*)&eg);
                    float2 ef1 = __half22float2(*(__half2*)&eg8);
                    float p0 = ex2(c[mfr][j][0] - m[mfr][0]) * ef0.x;
                    float p1 = ex2(c[mfr][j][1] - m[mfr][0]) * ef0.y;
                    float p2 = ex2(c[mfr][j][2] - m[mfr][1]) * ef1.x;
                    float p3 = ex2(c[mfr][j][3] - m[mfr][1]) * ef1.y;
                    pf[mfr][j >> 1][(j & 1) * 2 + 0] = h2u(__floats2half2_rn(p0, p1));
                    pf[mfr][j >> 1][(j & 1) * 2 + 1] = h2u(__floats2half2_rn(p2, p3));
                }
            }
        } else {
            float flc = (tt < ttA) ? fL : fR;
            #pragma unroll
            for (int mfr = 0; mfr < 2; mfr++) {
                float sh0 = m[mfr][0] - flc;
                float sh1 = m[mfr][1] - flc;
                #pragma unroll
                for (int j = 0; j < 4; j++) {
                    __half2 d0 = __floats2half2_rn(c[mfr][j][0] - sh0, c[mfr][j][1] - sh0);
                    __half2 d1 = __floats2half2_rn(c[mfr][j][2] - sh1, c[mfr][j][3] - sh1);
                    pf[mfr][j >> 1][(j & 1) * 2 + 0] = ex2h2(h2u(d0));
                    pf[mfr][j >> 1][(j & 1) * 2 + 1] = ex2h2(h2u(d1));
                }
            }
        }

        #pragma unroll
        for (int kc = 0; kc < 2; kc++) {
            unsigned vb0[4], vb1[4];
            uint32_t aV = sb + stoff + vAddr + (uint32_t)(kc * 16 * 80);
            LDM_X4T(vb0, aV);
            LDM_X4T(vb1, aV + 8 * 80);
            #pragma unroll
            for (int n = 0; n < 4; n++) {
                mma_f16(o[0][n], pf[0][kc], vb0[n], vb1[n]);
                mma_f16(o[1][n], pf[1][kc], vb0[n], vb1[n]);
            }
            mma_f16(o[0][4], pf[0][kc], bbone, bbone);
            mma_f16(o[1][4], pf[1][kc], bbone, bbone);
        }
    }

    __syncthreads();

    float* Os = (float*)&KVM[0][0];
    if (kh == 1) {
        #pragma unroll
        for (int mfr = 0; mfr < 2; mfr++) {
            int r0 = qg * 1344 + (mfr * 16 + g) * 42;
            int r1 = r0 + 8 * 42;
            #pragma unroll
            for (int n = 0; n < 5; n++) {
                float2 w0; w0.x = o[mfr][n][0]; w0.y = o[mfr][n][1];
                float2 w1; w1.x = o[mfr][n][2]; w1.y = o[mfr][n][3];
                *(float2*)&Os[r0 + n * 8 + 2 * tig] = w0;
                *(float2*)&Os[r1 + n * 8 + 2 * tig] = w1;
            }
            if (tig == 0) {
                Os[r0 + 40] = m[mfr][0];
                Os[r1 + 40] = m[mfr][1];
            }
        }
    }
    __syncthreads();
    if (kh == 0) {
        #pragma unroll
        for (int mfr = 0; mfr < 2; mfr++) {
            int r0 = qg * 1344 + (mfr * 16 + g) * 42;
            int r1 = r0 + 8 * 42;
            float mo0 = Os[r0 + 40], mo1 = Os[r1 + 40];
            float M0 = fmaxf(m[mfr][0], mo0);
            float M1 = fmaxf(m[mfr][1], mo1);
            float ws0 = ex2(m[mfr][0] - M0), wo0 = ex2(mo0 - M0);
            float ws1 = ex2(m[mfr][1] - M1), wo1 = ex2(mo1 - M1);
            #pragma unroll
            for (int n = 0; n < 4; n++) {
                float2 p0 = *(float2*)&Os[r0 + n * 8 + 2 * tig];
                float2 p1 = *(float2*)&Os[r1 + n * 8 + 2 * tig];
                float2 w0, w1;
                w0.x = o[mfr][n][0] * ws0 + p0.x * wo0;
                w0.y = o[mfr][n][1] * ws0 + p0.y * wo0;
                w1.x = o[mfr][n][2] * ws1 + p1.x * wo1;
                w1.y = o[mfr][n][3] * ws1 + p1.y * wo1;
                int rg = (s * B_ + b) * LQ_ + q0 + qg * 32 + mfr * 16 + g;
                int col = h * HD_ + n * 8 + 2 * tig;
                *(float2*)&opart[(size_t)rg * DIM_ + col] = w0;
                *(float2*)&opart[(size_t)(rg + 8) * DIM_ + col] = w1;
            }
            if (tig == 0) {
                float l0 = o[mfr][4][0] * ws0 + Os[r0 + 32] * wo0;
                float l1 = o[mfr][4][2] * ws1 + Os[r1 + 32] * wo1;
                int rg = (s * B_ + b) * LQ_ + q0 + qg * 32 + mfr * 16 + g;
                float* mlb0 = &mlpart[(size_t)rg * (H_ * 2) + h * 2];
                float* mlb1 = &mlpart[(size_t)(rg + 8) * (H_ * 2) + h * 2];
                mlb0[0] = M0; mlb0[1] = l0;
                mlb1[0] = M1; mlb1[1] = l1;
            }
        }
    }
}

// ---------------- split merge -> fp16 ctx ----------------
__global__ void merge_kernel(const float* __restrict__ opart,
                             const float* __restrict__ mlpart,
                             __half* __restrict__ ctxh) {
    int idx = blockIdx.x * blockDim.x + threadIdx.x;
    int row = idx >> 6;
    int d4 = (idx & 63) * 4;
    int h = d4 >> 5;
    const float* ml0 = &mlpart[(size_t)row * (H_ * 2) + h * 2];
    const float* ml1 = ml0 + (size_t)B_ * LQ_ * H_ * 2;
    float m0 = ml0[0], l0 = ml0[1], m1 = ml1[0], l1 = ml1[1];
    float M = fmaxf(m0, m1);
    float w0 = ex2(m0 - M), w1 = ex2(m1 - M);
    float inv = 1.0f / (l0 * w0 + l1 * w1);
    float4 a = *(const float4*)&opart[(size_t)row * DIM_ + d4];
    float4 bb = *(const float4*)&opart[(size_t)(B_ * LQ_ + row) * DIM_ + d4];
    uint2 u;
    u.x = h2u(__floats2half2_rn((a.x * w0 + bb.x * w1) * inv, (a.y * w0 + bb.y * w1) * inv));
    u.y = h2u(__floats2half2_rn((a.z * w0 + bb.z * w1) * inv, (a.w * w0 + bb.w * w1) * inv));
    *(uint2*)&ctxh[(size_t)row * DIM_ + d4] = u;
}

// ---------------- launch ----------------
extern "C" void kernel_launch(void* const* d_in, const int* in_sizes, int n_in,
                              void* d_out, int out_size) {
    const float* q          = (const float*)d_in[0];
    const float* kv         = (const float*)d_in[1];
    const float* in_proj_w  = (const float*)d_in[2];
    const float* in_proj_b  = (const float*)d_in[3];
    const float* out_proj_w = (const float*)d_in[4];
    const float* out_proj_b = (const float*)d_in[5];
    const float* rel_bias   = (const float*)d_in[6];
    const float* mask_scale = (const float*)d_in[7];
    float* out = (float*)d_out;

    __half *pQX, *pKVX, *pW16, *pWO16, *pQ, *pKV, *pEM, *pCH;
    float *pOP, *pML, *pF;
    cudaGetSymbolAddress((void**)&pQX,  g_qx);
    cudaGetSymbolAddress((void**)&pKVX, g_kvx);
    cudaGetSymbolAddress((void**)&pW16, g_w16);
    cudaGetSymbolAddress((void**)&pWO16, g_wo16);
    cudaGetSymbolAddress((void**)&pQ,  g_Qh);
    cudaGetSymbolAddress((void**)&pKV, g_KVh);
    cudaGetSymbolAddress((void**)&pEM, g_em);
    cudaGetSymbolAddress((void**)&pCH, g_ctxh);
    cudaGetSymbolAddress((void**)&pOP, g_op);
    cudaGetSymbolAddress((void**)&pML, g_ml);
    cudaGetSymbolAddress((void**)&pF,  g_far);

    const float attn_scale = 0.17677669529663687f * 1.4426950408889634f;

    emask_kernel<<<(LQ_ * T_) / 256, 256>>>(rel_bias, mask_scale, pEM, pF);

    cvt16<<<(B_ * LQ_ * DIM_ / 8) / 256, 256>>>(q, pQX);
    cvt16<<<(B_ * T_ * DIM_ / 8) / 256, 256>>>(kv, pKVX);
    cvt16<<<(3 * DIM_ * DIM_ / 8) / 256, 256>>>(in_proj_w, pW16);
    cvt16<<<(DIM_ * DIM_ / 8) / 256, 256>>>(out_proj_w, pWO16);

    gemm16h<true><<<dim3(DIM_ / 128, (B_ * LQ_) / 128), 256>>>(
        pQX, pW16, in_proj_b, pQ, DIM_, attn_scale);

    gemm16h<true><<<dim3((2 * DIM_) / 128, (B_ * T_) / 128), 256>>>(
        pKVX, pW16 + DIM_ * DIM_, in_proj_b + DIM_, pKV, 2 * DIM_, 1.0f);

    attn16<<<dim3(LQ_ / 64, H_, B_ * NSPLIT), 128>>>(pQ, pKV, pEM, pF, pOP, pML);

    merge_kernel<<<(B_ * LQ_ * DIM_ / 4) / 256, 256>>>(pOP, pML, pCH);

    gemm16h<false><<<dim3(DIM_ / 128, (B_ * LQ_) / 128), 256>>>(
        pCH, pWO16, out_proj_b, out, DIM_, 1.0f);
}

// round 17
// speedup vs baseline: 1.0952x; 1.0298x over previous
#include <cuda_runtime.h>
#include <cuda_fp16.h>
#include <math.h>
#include <stdint.h>

#define B_    8
#define H_    8
#define LQ_   512
#define T_    8192
#define DIM_  256
#define HD_   32
#define MAXREL_ 128
#define NSPLIT 2
#define TSPLIT (T_ / NSPLIT)
#define NTILES (TSPLIT / 64)
#define STEPF (8191.0f / 511.0f)

// ---------------- scratch ----------------
__device__ __half g_qx[B_ * LQ_ * DIM_];
__device__ __half g_kvx[B_ * T_ * DIM_];
__device__ __half g_w16[3 * DIM_ * DIM_];
__device__ __half g_wo16[DIM_ * DIM_];
__device__ __half g_Qh[B_ * LQ_ * DIM_];
__device__ __half g_KVh[B_ * T_ * 2 * DIM_];
__device__ __half g_em[LQ_ * T_];
__device__ __half g_ctxh[B_ * LQ_ * DIM_];
__device__ float  g_op[NSPLIT * B_ * LQ_ * DIM_];
__device__ float  g_ml[NSPLIT * B_ * LQ_ * H_ * 2];
__device__ float  g_far[2];

// ---------------- helpers ----------------
__device__ __forceinline__ void mma_f16(float c[4], const unsigned a[4], unsigned b0, unsigned b1) {
    asm volatile("mma.sync.aligned.m16n8k16.row.col.f32.f16.f16.f32 "
        "{%0,%1,%2,%3}, {%4,%5,%6,%7}, {%8,%9}, {%0,%1,%2,%3};"
        : "+f"(c[0]), "+f"(c[1]), "+f"(c[2]), "+f"(c[3])
        : "r"(a[0]), "r"(a[1]), "r"(a[2]), "r"(a[3]), "r"(b0), "r"(b1));
}
__device__ __forceinline__ unsigned h2u(__half2 h) { return *(unsigned*)&h; }
__device__ __forceinline__ uint32_t smem_u32(const void* p) {
    uint32_t a;
    asm("{ .reg .u64 t; cvta.to.shared.u64 t, %1; cvt.u32.u64 %0, t; }" : "=r"(a) : "l"(p));
    return a;
}
__device__ __forceinline__ float ex2(float x) {
    float r; asm("ex2.approx.f32 %0, %1;" : "=f"(r) : "f"(x)); return r;
}
__device__ __forceinline__ unsigned ex2h2(unsigned x) {
    unsigned r; asm("ex2.approx.f16x2 %0, %1;" : "=r"(r) : "r"(x)); return r;
}
#define LDM_X4(r, addr) \
    asm volatile("ldmatrix.sync.aligned.m8n8.x4.shared.b16 {%0,%1,%2,%3}, [%4];" \
        : "=r"((r)[0]), "=r"((r)[1]), "=r"((r)[2]), "=r"((r)[3]) : "r"(addr))
#define LDM_X4T(r, addr) \
    asm volatile("ldmatrix.sync.aligned.m8n8.x4.trans.shared.b16 {%0,%1,%2,%3}, [%4];" \
        : "=r"((r)[0]), "=r"((r)[1]), "=r"((r)[2]), "=r"((r)[3]) : "r"(addr))
#define CP16(dst, src) \
    asm volatile("cp.async.ca.shared.global [%0], [%1], 16;" :: "r"(dst), "l"(src))
#define CP_COMMIT() asm volatile("cp.async.commit_group;" ::: "memory")
#define CP_WAIT0()  asm volatile("cp.async.wait_group 0;" ::: "memory")

#define STG_SZ 19456
#define OFF_V  5120
#define OFF_M  10240

// ---------------- fused fp32 -> fp16 conversion (q | kv | w | wo) ----------------
#define NQ_  (B_ * LQ_ * DIM_)
#define NKV_ (B_ * T_ * DIM_)
#define NW_  (3 * DIM_ * DIM_)
#define NWO_ (DIM_ * DIM_)
__global__ void cvt_all(const float* __restrict__ q,  const float* __restrict__ kv,
                        const float* __restrict__ w,  const float* __restrict__ wo,
                        __half* __restrict__ qx, __half* __restrict__ kvx,
                        __half* __restrict__ w16, __half* __restrict__ wo16) {
    long i = (long)(blockIdx.x * blockDim.x + threadIdx.x) * 8;
    const float* src;
    __half* dst;
    long off;
    if (i < NQ_)                         { src = q;  dst = qx;  off = i; }
    else if (i < NQ_ + NKV_)             { src = kv; dst = kvx; off = i - NQ_; }
    else if (i < NQ_ + NKV_ + NW_)       { src = w;  dst = w16; off = i - NQ_ - NKV_; }
    else                                 { src = wo; dst = wo16; off = i - NQ_ - NKV_ - NW_; }
    float4 a = *(const float4*)&src[off];
    float4 b = *(const float4*)&src[off + 4];
    uint4 u;
    u.x = h2u(__floats2half2_rn(a.x, a.y)); u.y = h2u(__floats2half2_rn(a.z, a.w));
    u.z = h2u(__floats2half2_rn(b.x, b.y)); u.w = h2u(__floats2half2_rn(b.z, b.w));
    *(uint4*)&dst[off] = u;
}
#define NCVT_TOTAL (NQ_ + NKV_ + NW_ + NWO_)

// ---------------- exp(mask) precompute, band-only grid ----------------
#define MBAND 3456
__global__ void emask_kernel(const float* __restrict__ rel_bias,
                             const float* __restrict__ mask_scale,
                             __half* __restrict__ em,
                             float* __restrict__ farc) {
    int idx = blockIdx.x * blockDim.x + threadIdx.x;
    if (idx == 0) {
        const float L2E = 1.4426950408889634f;
        float ms = mask_scale[0];
        farc[0] = ms * (rel_bias[0] + __logf(1e-6f)) * L2E;
        farc[1] = ms * (rel_bias[2 * MAXREL_] + __logf(1e-6f)) * L2E;
    }
    int i = idx / MBAND;
    int off = idx - i * MBAND;
    float tau = (float)i * STEPF;
    int t0 = (int)tau - 1727;
    t0 = max(0, min(T_ - MBAND, t0));
    int t = t0 + off;
    float dt = (float)t - tau;
    if (fabsf(dt) > 1664.0f) return;
    float dtc = fminf(fmaxf(dt, -(float)MAXREL_), (float)MAXREL_);
    int bi = (int)dtc + MAXREL_;
    float bias = rel_bias[bi];
    float z = dt * (1.0f / 64.0f);
    float lg = __logf(__expf(-0.5f * z * z) + 1e-6f);
    em[(size_t)i * T_ + t] = __float2half_rn(__expf(mask_scale[0] * (bias + lg)));
}

// ---------------- fp16-input GEMM, cp.async double-buffered, single barrier/chunk ----------------
template<bool OHALF>
__global__ void __launch_bounds__(256, 2) gemm16h(const __half* __restrict__ A,
                                                  const __half* __restrict__ W,
                                                  const float* __restrict__ bias,
                                                  void* __restrict__ outp,
                                                  int ldo, float scale) {
    __shared__ __align__(16) char SB[2][2 * 10240];
    int tid = threadIdx.x;
    int lane = tid & 31, warp = tid >> 5;
    int wm = warp >> 1, wn = warp & 1;
    int g = lane >> 2, tig = lane & 3;
    int row0 = blockIdx.y * 128, col0 = blockIdx.x * 128;
    uint32_t sb = smem_u32(&SB[0][0]);

    float c[2][8][4];
    #pragma unroll
    for (int i = 0; i < 2; i++)
        #pragma unroll
        for (int j = 0; j < 8; j++)
            #pragma unroll
            for (int v = 0; v < 4; v++) c[i][j][v] = 0.0f;

    int r = tid >> 2, seg = tid & 3;
    const __half* pA = A + (size_t)(row0 + r) * 256 + seg * 8;
    const __half* pW = W + (size_t)(col0 + r) * 256 + seg * 8;
    uint32_t dA = sb + (uint32_t)(r * 80 + seg * 16);
    uint32_t dW = dA + 10240;

    uint32_t aArow = (uint32_t)(wm * 32 + (lane & 7) + ((lane >> 3) & 1) * 8);
    uint32_t aAseg = (uint32_t)(lane >> 4);
    uint32_t aBrow = (uint32_t)(wn * 64 + (lane >> 3) * 8 + (lane & 7));

    CP16(dA, pA); CP16(dA + 64 * 80, pA + 64 * 256);
    CP16(dW, pW); CP16(dW + 64 * 80, pW + 64 * 256);
    CP_COMMIT();

    #pragma unroll 1
    for (int kc8 = 0; kc8 < 8; kc8++) {
        CP_WAIT0();
        __syncthreads();   // all threads done with prev chunk's compute; staged data visible
        if (kc8 + 1 < 8) {
            uint32_t dst = (uint32_t)(((kc8 & 1) ^ 1) * 20480);
            int k0 = (kc8 + 1) * 32;
            CP16(dA + dst, pA + k0); CP16(dA + dst + 64 * 80, pA + 64 * 256 + k0);
            CP16(dW + dst, pW + k0); CP16(dW + dst + 64 * 80, pW + 64 * 256 + k0);
            CP_COMMIT();
        }
        uint32_t sbA = sb + (uint32_t)((kc8 & 1) * 20480);
        uint32_t sbW = sbA + 10240;
        #pragma unroll
        for (int kc = 0; kc < 2; kc++) {
            unsigned af0[4], af1[4];
            LDM_X4(af0, sbA + aArow * 80 + (kc * 2 + aAseg) * 16);
            LDM_X4(af1, sbA + (aArow + 16) * 80 + (kc * 2 + aAseg) * 16);
            unsigned b0a[4], b1a[4], b0b[4], b1b[4];
            uint32_t aB = sbW + aBrow * 80 + kc * 32;
            LDM_X4(b0a, aB);
            LDM_X4(b1a, aB + 16);
            LDM_X4(b0b, aB + 32 * 80);
            LDM_X4(b1b, aB + 32 * 80 + 16);
            #pragma unroll
            for (int j = 0; j < 8; j++) {
                unsigned bb0 = (j < 4) ? b0a[j] : b0b[j - 4];
                unsigned bb1 = (j < 4) ? b1a[j] : b1b[j - 4];
                mma_f16(c[0][j], af0, bb0, bb1);
                mma_f16(c[1][j], af1, bb0, bb1);
            }
        }
    }

    #pragma unroll
    for (int j = 0; j < 8; j++) {
        int colg = col0 + wn * 64 + j * 8 + 2 * tig;
        float2 bv = *(const float2*)&bias[colg];
        #pragma unroll
        for (int i = 0; i < 2; i++) {
            int rowg = row0 + wm * 32 + i * 16 + g;
            float x0 = scale * (c[i][j][0] + bv.x);
            float y0 = scale * (c[i][j][1] + bv.y);
            float x1 = scale * (c[i][j][2] + bv.x);
            float y1 = scale * (c[i][j][3] + bv.y);
            if (OHALF) {
                __half* o = (__half*)outp;
                *(unsigned*)&o[(size_t)rowg * ldo + colg] = h2u(__floats2half2_rn(x0, y0));
                *(unsigned*)&o[(size_t)(rowg + 8) * ldo + colg] = h2u(__floats2half2_rn(x1, y1));
            } else {
                float* o = (float*)outp;
                float2 r0; r0.x = x0; r0.y = y0;
                float2 r1; r1.x = x1; r1.y = y1;
                *(float2*)&o[(size_t)rowg * ldo + colg] = r0;
                *(float2*)&o[(size_t)(rowg + 8) * ldo + colg] = r1;
            }
        }
    }
}

// ---------------- flash attention (R16 version, measured) ----------------
__global__ void __launch_bounds__(128, 4) attn16(const __half* __restrict__ Qh,
                                                 const __half* __restrict__ KVh,
                                                 const __half* __restrict__ emh,
                                                 const float* __restrict__ farc,
                                                 float* __restrict__ opart,
                                                 float* __restrict__ mlpart) {
    __shared__ __align__(16) char KVM[2][STG_SZ];

    int tid = threadIdx.x;
    int lane = tid & 31, warp = tid >> 5;
    int qg = warp >> 1, kh = warp & 1;
    int g = lane >> 2, tig = lane & 3;
    int q0 = blockIdx.x * 64, h = blockIdx.y;
    int b = blockIdx.z >> 1, s = blockIdx.z & 1;
    int tb = s * TSPLIT;
    uint32_t sb = smem_u32(&KVM[0][0]);

    float tauMin = (float)q0 * STEPF;
    float tauMax = (float)(q0 + 63) * STEPF;
    int ttA = (int)floorf((tauMin - 448.0f - 63.0f - (float)tb) * (1.0f / 64.0f)) + 1;
    int ttB = (int)ceilf((tauMax + 448.0f - (float)tb) * (1.0f / 64.0f));
    ttA = max(0, min(NTILES, ttA));
    ttB = max(ttA, min(NTILES, ttB));
    float fL = farc[0], fR = farc[1];

    unsigned qf[2][2][4];
    #pragma unroll
    for (int mfr = 0; mfr < 2; mfr++) {
        const __half* qb0 = &Qh[(size_t)(b * LQ_ + q0 + qg * 32 + mfr * 16 + g) * DIM_ + h * HD_ + 2 * tig];
        #pragma unroll
        for (int kc = 0; kc < 2; kc++) {
            const __half* qb = qb0 + kc * 16;
            qf[mfr][kc][0] = *(const unsigned*)qb;
            qf[mfr][kc][1] = *(const unsigned*)(qb + 8 * DIM_);
            qf[mfr][kc][2] = *(const unsigned*)(qb + 8);
            qf[mfr][kc][3] = *(const unsigned*)(qb + 8 * DIM_ + 8);
        }
    }

    int srow = tid >> 2, seg = tid & 3;
    uint32_t dK0 = sb + (uint32_t)(srow * 80 + seg * 16);
    uint32_t dK1 = dK0 + 32 * 80;
    const __half* sKV = &KVh[(size_t)(b * T_ + tb + srow) * (2 * DIM_) + h * HD_ + seg * 8];
    int mrow = tid >> 1, mseg = (tid & 1) * 64;
    uint32_t dM = sb + OFF_M + (uint32_t)(mrow * 144 + mseg);
    const __half* sM = &emh[(size_t)(q0 + mrow) * T_ + tb + mseg / 2];

    uint32_t kAddr = (uint32_t)((kh * 32 + (lane >> 3) * 8 + (lane & 7)) * 80);
    uint32_t vAddr = (uint32_t)(OFF_V + (kh * 32 + (lane & 7)) * 80 + (lane >> 3) * 16);
    uint32_t mAddrB = (uint32_t)(OFF_M + (qg * 32 + (lane & 15)) * 144 + kh * 64 + (lane >> 4) * 16);

    unsigned bbone = (g == 0) ? 0x3C003C00u : 0u;

    float m[2][2], o[2][5][4];
    #pragma unroll
    for (int i = 0; i < 2; i++)
        #pragma unroll
        for (int j = 0; j < 2; j++) m[i][j] = -1e30f;
    #pragma unroll
    for (int i = 0; i < 2; i++)
        #pragma unroll
        for (int n = 0; n < 5; n++)
            #pragma unroll
            for (int v = 0; v < 4; v++) o[i][n][v] = 0.0f;

    {
        const __half* p = sKV;
        CP16(dK0, p); CP16(dK1, p + (size_t)32 * 2 * DIM_);
        CP16(dK0 + OFF_V, p + DIM_); CP16(dK1 + OFF_V, p + (size_t)32 * 2 * DIM_ + DIM_);
        if (0 >= ttA && 0 < ttB) {
            const __half* pm = sM;
            CP16(dM, pm); CP16(dM + 16, pm + 8); CP16(dM + 32, pm + 16); CP16(dM + 48, pm + 24);
        }
        CP_COMMIT();
    }

    for (int tt = 0; tt < NTILES; tt++) {
        uint32_t stoff = (uint32_t)((tt & 1) * STG_SZ);
        bool mixed = (tt >= ttA) && (tt < ttB);
        CP_WAIT0();
        __syncthreads();

        if (tt + 1 < NTILES) {
            uint32_t dst = (uint32_t)(((tt & 1) ^ 1) * STG_SZ);
            const __half* p = sKV + (size_t)(tt + 1) * 64 * 2 * DIM_;
            CP16(dK0 + dst, p); CP16(dK1 + dst, p + (size_t)32 * 2 * DIM_);
            CP16(dK0 + dst + OFF_V, p + DIM_); CP16(dK1 + dst + OFF_V, p + (size_t)32 * 2 * DIM_ + DIM_);
            if (tt + 1 >= ttA && tt + 1 < ttB) {
                const __half* pm = sM + (size_t)(tt + 1) * 64;
                uint32_t dMd = dM + dst;
                CP16(dMd, pm); CP16(dMd + 16, pm + 8); CP16(dMd + 32, pm + 16); CP16(dMd + 48, pm + 24);
            }
            CP_COMMIT();
        }

        float c[2][4][4];
        #pragma unroll
        for (int mfr = 0; mfr < 2; mfr++)
            #pragma unroll
            for (int j = 0; j < 4; j++)
                #pragma unroll
                for (int v = 0; v < 4; v++) c[mfr][j][v] = 0.0f;
        #pragma unroll
        for (int kc = 0; kc < 2; kc++) {
            unsigned kb0[4], kb1[4];
            uint32_t aB = sb + stoff + kAddr + kc * 32;
            LDM_X4(kb0, aB);
            LDM_X4(kb1, aB + 16);
            #pragma unroll
            for (int j = 0; j < 4; j++) {
                mma_f16(c[0][j], qf[0][kc], kb0[j], kb1[j]);
                mma_f16(c[1][j], qf[1][kc], kb0[j], kb1[j]);
            }
        }

        float mold[2][2];
        bool upd = false;
        #pragma unroll
        for (int mfr = 0; mfr < 2; mfr++)
            #pragma unroll
            for (int hi = 0; hi < 2; hi++) {
                float mx = fmaxf(c[mfr][0][hi * 2], c[mfr][0][hi * 2 + 1]);
                #pragma unroll
                for (int j = 1; j < 4; j++)
                    mx = fmaxf(mx, fmaxf(c[mfr][j][hi * 2], c[mfr][j][hi * 2 + 1]));
                mx = fmaxf(mx, __shfl_xor_sync(0xffffffffu, mx, 1));
                mx = fmaxf(mx, __shfl_xor_sync(0xffffffffu, mx, 2));
                mold[mfr][hi] = m[mfr][hi];
                float mn = fmaxf(m[mfr][hi], mx);
                upd |= (mn > m[mfr][hi]);
                m[mfr][hi] = mn;
            }

        if (__ballot_sync(0xffffffffu, upd)) {
            #pragma unroll
            for (int mfr = 0; mfr < 2; mfr++) {
                float a0 = ex2(mold[mfr][0] - m[mfr][0]);
                float a1 = ex2(mold[mfr][1] - m[mfr][1]);
                #pragma unroll
                for (int n = 0; n < 5; n++) {
                    o[mfr][n][0] *= a0; o[mfr][n][1] *= a0;
                    o[mfr][n][2] *= a1; o[mfr][n][3] *= a1;
                }
            }
        }

        unsigned pf[2][2][4];
        if (mixed) {
            #pragma unroll
            for (int mfr = 0; mfr < 2; mfr++) {
                unsigned me0[4], me1[4];
                uint32_t aM = sb + stoff + mAddrB + (uint32_t)(mfr * 16 * 144);
                LDM_X4(me0, aM);
                LDM_X4(me1, aM + 32);
                #pragma unroll
                for (int j = 0; j < 4; j++) {
                    unsigned eg  = (j < 2) ? me0[(j & 1) * 2]     : me1[(j & 1) * 2];
                    unsigned eg8 = (j < 2) ? me0[(j & 1) * 2 + 1] : me1[(j & 1) * 2 + 1];
                    float2 ef0 = __half22float2(*(__half2*)&eg);
                    float2 ef1 = __half22float2(*(__half2*)&eg8);
                    float p0 = ex2(c[mfr][j][0] - m[mfr][0]) * ef0.x;
                    float p1 = ex2(c[mfr][j][1] - m[mfr][0]) * ef0.y;
                    float p2 = ex2(c[mfr][j][2] - m[mfr][1]) * ef1.x;
                    float p3 = ex2(c[mfr][j][3] - m[mfr][1]) * ef1.y;
                    pf[mfr][j >> 1][(j & 1) * 2 + 0] = h2u(__floats2half2_rn(p0, p1));
                    pf[mfr][j >> 1][(j & 1) * 2 + 1] = h2u(__floats2half2_rn(p2, p3));
                }
            }
        } else {
            float flc = (tt < ttA) ? fL : fR;
            #pragma unroll
            for (int mfr = 0; mfr < 2; mfr++) {
                float sh0 = m[mfr][0] - flc;
                float sh1 = m[mfr][1] - flc;
                #pragma unroll
                for (int j = 0; j < 4; j++) {
                    __half2 d0 = __floats2half2_rn(c[mfr][j][0] - sh0, c[mfr][j][1] - sh0);
                    __half2 d1 = __floats2half2_rn(c[mfr][j][2] - sh1, c[mfr][j][3] - sh1);
                    pf[mfr][j >> 1][(j & 1) * 2 + 0] = ex2h2(h2u(d0));
                    pf[mfr][j >> 1][(j & 1) * 2 + 1] = ex2h2(h2u(d1));
                }
            }
        }

        #pragma unroll
        for (int kc = 0; kc < 2; kc++) {
            unsigned vb0[4], vb1[4];
            uint32_t aV = sb + stoff + vAddr + (uint32_t)(kc * 16 * 80);
            LDM_X4T(vb0, aV);
            LDM_X4T(vb1, aV + 8 * 80);
            #pragma unroll
            for (int n = 0; n < 4; n++) {
                mma_f16(o[0][n], pf[0][kc], vb0[n], vb1[n]);
                mma_f16(o[1][n], pf[1][kc], vb0[n], vb1[n]);
            }
            mma_f16(o[0][4], pf[0][kc], bbone, bbone);
            mma_f16(o[1][4], pf[1][kc], bbone, bbone);
        }
    }

    __syncthreads();

    float* Os = (float*)&KVM[0][0];
    if (kh == 1) {
        #pragma unroll
        for (int mfr = 0; mfr < 2; mfr++) {
            int r0 = qg * 1344 + (mfr * 16 + g) * 42;
            int r1 = r0 + 8 * 42;
            #pragma unroll
            for (int n = 0; n < 5; n++) {
                float2 w0; w0.x = o[mfr][n][0]; w0.y = o[mfr][n][1];
                float2 w1; w1.x = o[mfr][n][2]; w1.y = o[mfr][n][3];
                *(float2*)&Os[r0 + n * 8 + 2 * tig] = w0;
                *(float2*)&Os[r1 + n * 8 + 2 * tig] = w1;
            }
            if (tig == 0) {
                Os[r0 + 40] = m[mfr][0];
                Os[r1 + 40] = m[mfr][1];
            }
        }
    }
    __syncthreads();
    if (kh == 0) {
        #pragma unroll
        for (int mfr = 0; mfr < 2; mfr++) {
            int r0 = qg * 1344 + (mfr * 16 + g) * 42;
            int r1 = r0 + 8 * 42;
            float mo0 = Os[r0 + 40], mo1 = Os[r1 + 40];
            float M0 = fmaxf(m[mfr][0], mo0);
            float M1 = fmaxf(m[mfr][1], mo1);
            float ws0 = ex2(m[mfr][0] - M0), wo0 = ex2(mo0 - M0);
            float ws1 = ex2(m[mfr][1] - M1), wo1 = ex2(mo1 - M1);
            #pragma unroll
            for (int n = 0; n < 4; n++) {
                float2 p0 = *(float2*)&Os[r0 + n * 8 + 2 * tig];
                float2 p1 = *(float2*)&Os[r1 + n * 8 + 2 * tig];
                float2 w0, w1;
                w0.x = o[mfr][n][0] * ws0 + p0.x * wo0;
                w0.y = o[mfr][n][1] * ws0 + p0.y * wo0;
                w1.x = o[mfr][n][2] * ws1 + p1.x * wo1;
                w1.y = o[mfr][n][3] * ws1 + p1.y * wo1;
                int rg = (s * B_ + b) * LQ_ + q0 + qg * 32 + mfr * 16 + g;
                int col = h * HD_ + n * 8 + 2 * tig;
                *(float2*)&opart[(size_t)rg * DIM_ + col] = w0;
                *(float2*)&opart[(size_t)(rg + 8) * DIM_ + col] = w1;
            }
            if (tig == 0) {
                float l0 = o[mfr][4][0] * ws0 + Os[r0 + 32] * wo0;
                float l1 = o[mfr][4][2] * ws1 + Os[r1 + 32] * wo1;
                int rg = (s * B_ + b) * LQ_ + q0 + qg * 32 + mfr * 16 + g;
                float* mlb0 = &mlpart[(size_t)rg * (H_ * 2) + h * 2];
                float* mlb1 = &mlpart[(size_t)(rg + 8) * (H_ * 2) + h * 2];
                mlb0[0] = M0; mlb0[1] = l0;
                mlb1[0] = M1; mlb1[1] = l1;
            }
        }
    }
}

// ---------------- split merge -> fp16 ctx ----------------
__global__ void merge_kernel(const float* __restrict__ opart,
                             const float* __restrict__ mlpart,
                             __half* __restrict__ ctxh) {
    int idx = blockIdx.x * blockDim.x + threadIdx.x;
    int row = idx >> 6;
    int d4 = (idx & 63) * 4;
    int h = d4 >> 5;
    const float* ml0 = &mlpart[(size_t)row * (H_ * 2) + h * 2];
    const float* ml1 = ml0 + (size_t)B_ * LQ_ * H_ * 2;
    float m0 = ml0[0], l0 = ml0[1], m1 = ml1[0], l1 = ml1[1];
    float M = fmaxf(m0, m1);
    float w0 = ex2(m0 - M), w1 = ex2(m1 - M);
    float inv = 1.0f / (l0 * w0 + l1 * w1);
    float4 a = *(const float4*)&opart[(size_t)row * DIM_ + d4];
    float4 bb = *(const float4*)&opart[(size_t)(B_ * LQ_ + row) * DIM_ + d4];
    uint2 u;
    u.x = h2u(__floats2half2_rn((a.x * w0 + bb.x * w1) * inv, (a.y * w0 + bb.y * w1) * inv));
    u.y = h2u(__floats2half2_rn((a.z * w0 + bb.z * w1) * inv, (a.w * w0 + bb.w * w1) * inv));
    *(uint2*)&ctxh[(size_t)row * DIM_ + d4] = u;
}

// ---------------- launch ----------------
extern "C" void kernel_launch(void* const* d_in, const int* in_sizes, int n_in,
                              void* d_out, int out_size) {
    const float* q          = (const float*)d_in[0];
    const float* kv         = (const float*)d_in[1];
    const float* in_proj_w  = (const float*)d_in[2];
    const float* in_proj_b  = (const float*)d_in[3];
    const float* out_proj_w = (const float*)d_in[4];
    const float* out_proj_b = (const float*)d_in[5];
    const float* rel_bias   = (const float*)d_in[6];
    const float* mask_scale = (const float*)d_in[7];
    float* out = (float*)d_out;

    __half *pQX, *pKVX, *pW16, *pWO16, *pQ, *pKV, *pEM, *pCH;
    float *pOP, *pML, *pF;
    cudaGetSymbolAddress((void**)&pQX,  g_qx);
    cudaGetSymbolAddress((void**)&pKVX, g_kvx);
    cudaGetSymbolAddress((void**)&pW16, g_w16);
    cudaGetSymbolAddress((void**)&pWO16, g_wo16);
    cudaGetSymbolAddress((void**)&pQ,  g_Qh);
    cudaGetSymbolAddress((void**)&pKV, g_KVh);
    cudaGetSymbolAddress((void**)&pEM, g_em);
    cudaGetSymbolAddress((void**)&pCH, g_ctxh);
    cudaGetSymbolAddress((void**)&pOP, g_op);
    cudaGetSymbolAddress((void**)&pML, g_ml);
    cudaGetSymbolAddress((void**)&pF,  g_far);

    const float attn_scale = 0.17677669529663687f * 1.4426950408889634f;

    emask_kernel<<<(LQ_ * MBAND) / 256, 256>>>(rel_bias, mask_scale, pEM, pF);

    cvt_all<<<(NCVT_TOTAL / 8) / 256, 256>>>(q, kv, in_proj_w, out_proj_w,
                                             pQX, pKVX, pW16, pWO16);

    gemm16h<true><<<dim3(DIM_ / 128, (B_ * LQ_) / 128), 256>>>(
        pQX, pW16, in_proj_b, pQ, DIM_, attn_scale);

    gemm16h<true><<<dim3((2 * DIM_) / 128, (B_ * T_) / 128), 256>>>(
        pKVX, pW16 + DIM_ * DIM_, in_proj_b + DIM_, pKV, 2 * DIM_, 1.0f);

    attn16<<<dim3(LQ_ / 64, H_, B_ * NSPLIT), 128>>>(pQ, pKV, pEM, pF, pOP, pML);

    merge_kernel<<<(B_ * LQ_ * DIM_ / 4) / 256, 256>>>(pOP, pML, pCH);

    gemm16h<false><<<dim3(DIM_ / 128, (B_ * LQ_) / 128), 256>>>(
        pCH, pWO16, out_proj_b, out, DIM_, 1.0f);
}